// round 12
// baseline (speedup 1.0000x reference)
#include <cuda_runtime.h>
#include <cuda_fp16.h>
#include <stdint.h>

// GraphSAGE 4-layer, dense adj. N=8192, F: 256->128->128->64.
// h = act( h@W_self + adj @ (h@W_neigh) + b ).
// R12: 1-term fp16 aggregation on the PROVEN R10 skeleton (2-stage A with
// register prefetch + STS, 3-stage cp.async B ring, split-K warps, smem
// k-merge). Layer 1 additionally writes the packed fp16 adj to g_adjh
// (one fused STG); layers 2-4 load A as uint4 fp16 from g_adjh (no cvt,
// half the A DRAM bytes). No new sync structure vs R10.

static constexpr int MROWS = 8192;
static constexpr float A_SCALE = 4096.0f;
static constexpr float A_INV   = 1.0f / 4096.0f;

__device__ float g_y [8192 * 128];
__device__ float g_h1[8192 * 128];
__device__ float g_h2[8192 * 128];
__device__ __half g_zh[8192 * 128];
__device__ __half g_adjh[(size_t)8192 * 8192];   // scaled fp16 adj (134 MB)

__device__ __forceinline__ uint32_t smem_u32(const void* p) {
    uint32_t a;
    asm("{ .reg .u64 t; cvta.to.shared.u64 t, %1; cvt.u32.u64 %0, t; }"
        : "=r"(a) : "l"(p));
    return a;
}
__device__ __forceinline__ uint32_t packh2(float a, float b) {
    __half2 t = __floats2half2_rn(a, b);
    return *reinterpret_cast<uint32_t*>(&t);
}
__device__ __forceinline__ void ldsm_x4(uint32_t* r, uint32_t addr) {
    asm volatile("ldmatrix.sync.aligned.m8n8.x4.shared.b16 {%0,%1,%2,%3}, [%4];"
                 : "=r"(r[0]), "=r"(r[1]), "=r"(r[2]), "=r"(r[3]) : "r"(addr));
}
__device__ __forceinline__ void ldsm_x4_t(uint32_t* r, uint32_t addr) {
    asm volatile("ldmatrix.sync.aligned.m8n8.x4.trans.shared.b16 {%0,%1,%2,%3}, [%4];"
                 : "=r"(r[0]), "=r"(r[1]), "=r"(r[2]), "=r"(r[3]) : "r"(addr));
}
__device__ __forceinline__ void mma_f16(float* d, const uint32_t* a,
                                        uint32_t b0, uint32_t b1) {
    asm volatile(
        "mma.sync.aligned.m16n8k16.row.col.f32.f16.f16.f32 "
        "{%0,%1,%2,%3}, {%4,%5,%6,%7}, {%8,%9}, {%0,%1,%2,%3};"
        : "+f"(d[0]), "+f"(d[1]), "+f"(d[2]), "+f"(d[3])
        : "r"(a[0]), "r"(a[1]), "r"(a[2]), "r"(a[3]), "r"(b0), "r"(b1));
}
__device__ __forceinline__ void cp16(uint32_t dst, const void* src) {
    asm volatile("cp.async.ca.shared.global [%0], [%1], 16;" :: "r"(dst), "l"(src));
}
#define CP_COMMIT() asm volatile("cp.async.commit_group;" ::: "memory")
#define CP_WAIT1()  asm volatile("cp.async.wait_group 1;" ::: "memory")

// ── aggregation: out = act(adj @ z + y); 512 threads, split-K warps ──
// CVT: A from fp32 adjf (convert + store fp16 copy to adjh).
// !CVT: A loaded as fp16 uint4 from adjh.
template <int BN, bool CVT>
__global__ __launch_bounds__(512) void agg_k(
    const float* __restrict__ adjf,
    __half* __restrict__ adjh,
    const __half* __restrict__ zh,
    const float* __restrict__ y,
    float* __restrict__ out,
    int relu)
{
    constexpr int NT = 512;
    constexpr int BM = 64, BK = 64, NCH = MROWS / BK;
    constexpr int LDA = 144;                       // 128B fp16 row + 16B pad
    constexpr int ATILE = BM * LDA;                // 9216
    constexpr int LDB = BN * 2 + 16;
    constexpr int BTILE = BK * LDB;
    constexpr int BOFF = 2 * ATILE;                // A: 2 stages (as in R10)
    constexpr int CW = BN / 4;
    constexpr int NTN = CW / 8;                    // 4 / 2
    constexpr int NBL = NTN / 2;                   // 2 / 1
    constexpr int NCPB = BK * BN * 2 / 16;         // B cp16 per chunk
    constexpr int BCP = (NCPB + NT - 1) / NT;      // 2 / 1
    constexpr int CPRB = BN / 8;

    extern __shared__ __align__(128) char sm[];
    const uint32_t smb = smem_u32(sm);
    const int tid = threadIdx.x, m0 = blockIdx.x * BM;
    const int w = tid >> 5, lane = tid & 31;
    const int kw = w >> 3, wi = w & 7;
    const int wr = wi >> 2, wc = wi & 3;

    float acc[2][NTN][4];
#pragma unroll
    for (int mt = 0; mt < 2; mt++)
#pragma unroll
        for (int nt = 0; nt < NTN; nt++)
#pragma unroll
            for (int q = 0; q < 4; q++) acc[mt][nt][q] = 0.f;

    float4 raf[2];     // CVT prefetch
    uint4  rah;        // !CVT prefetch

    auto prefA = [&](int chunk) {
        const size_t kb = (size_t)chunk * BK;
        if (CVT) {
#pragma unroll
            for (int u = 0; u < 2; u++) {
                int id = tid + u * NT, row = id >> 4, c = id & 15;
                raf[u] = *reinterpret_cast<const float4*>(
                    adjf + (size_t)(m0 + row) * MROWS + kb + c * 4);
            }
        } else {
            int row = tid >> 3, c = tid & 7;
            rah = *reinterpret_cast<const uint4*>(
                adjh + (size_t)(m0 + row) * MROWS + kb + c * 8);
        }
    };
    auto commitA = [&](int sa, int chunk) {
        const size_t kb = (size_t)chunk * BK;
        if (CVT) {
#pragma unroll
            for (int u = 0; u < 2; u++) {
                int id = tid + u * NT, row = id >> 4, c = id & 15;
                uint32_t h01 = packh2(raf[u].x * A_SCALE, raf[u].y * A_SCALE);
                uint32_t h23 = packh2(raf[u].z * A_SCALE, raf[u].w * A_SCALE);
                uint32_t off = (uint32_t)(row * LDA + c * 8);
                *reinterpret_cast<uint2*>(sm + sa * ATILE + off) =
                    make_uint2(h01, h23);
                *reinterpret_cast<uint2*>(
                    adjh + (size_t)(m0 + row) * MROWS + kb + c * 4) =
                    make_uint2(h01, h23);
            }
        } else {
            int row = tid >> 3, c = tid & 7;
            *reinterpret_cast<uint4*>(sm + sa * ATILE + row * LDA + c * 16) = rah;
        }
    };
    auto issueB = [&](int chunk) {
        const uint32_t base = smb + BOFF + (chunk % 3) * BTILE;
        const size_t kb = (size_t)chunk * BK;
#pragma unroll
        for (int u = 0; u < BCP; u++) {
            int id = tid + u * NT;
            if (NCPB % NT == 0 || id < NCPB) {
                int krow = id / CPRB, c = id % CPRB;
                cp16(base + (uint32_t)(krow * LDB + c * 16),
                     zh + (kb + krow) * BN + c * 8);
            }
        }
    };

    const uint32_t a_lrow =
        (uint32_t)(wr * 32 + (lane & 15)) * LDA + (lane >> 4) * 16;

    auto compute = [&](int sa, int sb) {
        const uint32_t ab = smb + sa * ATILE;
        const uint32_t bb = smb + BOFF + sb * BTILE;
#pragma unroll
        for (int s = 0; s < 2; s++) {
            const int ks = kw * 2 + s;
            uint32_t ah[2][4];
#pragma unroll
            for (int mt = 0; mt < 2; mt++)
                ldsm_x4(ah[mt], ab + a_lrow + mt * (16 * LDA) + ks * 32);
            uint32_t zb[NBL][4];
#pragma unroll
            for (int bt = 0; bt < NBL; bt++) {
                int krow = ks * 16 + (lane & 15);
                int ncol = wc * CW + bt * 16 + (lane >> 4) * 8;
                ldsm_x4_t(zb[bt], bb + (uint32_t)(krow * LDB + ncol * 2));
            }
#pragma unroll
            for (int mt = 0; mt < 2; mt++)
#pragma unroll
                for (int nt = 0; nt < NTN; nt++) {
                    const int g = nt >> 1, p = (nt & 1) * 2;
                    mma_f16(acc[mt][nt], ah[mt], zb[g][p], zb[g][p + 1]);
                }
        }
    };

    // R10 mainloop, verbatim
    issueB(0); CP_COMMIT();
    issueB(1); CP_COMMIT();
    prefA(0);
    commitA(0, 0);
    prefA(1);

    for (int i = 0; i < NCH; i++) {
        const int sa = i & 1, sb = i % 3;
        CP_WAIT1();
        __syncthreads();
        compute(sa, sb);
        if (i + 2 < NCH) { issueB(i + 2); CP_COMMIT(); }
        if (i + 1 < NCH) {
            commitA((i + 1) & 1, i + 1);
            if (i + 2 < NCH) prefA(i + 2);
        }
    }

    // merge k-halves
    __syncthreads();
    float* ps = reinterpret_cast<float*>(sm);
    if (kw == 1) {
#pragma unroll
        for (int mt = 0; mt < 2; mt++)
#pragma unroll
            for (int nt = 0; nt < NTN; nt++)
#pragma unroll
                for (int q = 0; q < 4; q++)
                    ps[((((wi * 2 + mt) * NTN + nt) * 4) + q) * 32 + lane] =
                        acc[mt][nt][q];
    }
    __syncthreads();
    if (kw == 0) {
        const int g = lane >> 2, cp2 = (lane & 3) * 2;
#pragma unroll
        for (int mt = 0; mt < 2; mt++) {
            const int r0 = m0 + wr * 32 + mt * 16 + g;
#pragma unroll
            for (int nt = 0; nt < NTN; nt++) {
                const int col = wc * CW + nt * 8 + cp2;
                float p[4];
#pragma unroll
                for (int q = 0; q < 4; q++)
                    p[q] = acc[mt][nt][q] +
                        ps[((((wi * 2 + mt) * NTN + nt) * 4) + q) * 32 + lane];
#pragma unroll
                for (int half = 0; half < 2; half++) {
                    const size_t row = (size_t)(r0 + half * 8);
                    float2 yv = *reinterpret_cast<const float2*>(y + row * BN + col);
                    float v0 = p[2 * half + 0] * A_INV + yv.x;
                    float v1 = p[2 * half + 1] * A_INV + yv.y;
                    if (relu) { v0 = fmaxf(v0, 0.f); v1 = fmaxf(v1, 0.f); }
                    *reinterpret_cast<float2*>(out + row * BN + col) =
                        make_float2(v0, v1);
                }
            }
        }
    }
}

// ── fused projection: y = A@W[0:K] + b ; z = A@W[K:2K] -> fp16 ──
template <int BN>
__global__ __launch_bounds__(256, 2) void proj_k(
    const float* __restrict__ A,
    const float* __restrict__ W,
    const float* __restrict__ bias,
    float* __restrict__ yout,
    __half* __restrict__ zh,
    int K)
{
    constexpr int NT = 256, BM = 32, BK = 32, TM = 2, TN = BN / 16;
    constexpr int BF4 = (BK * BN / 4) / NT;
    __shared__ float As[BK][BM];
    __shared__ float Bs[BK][BN];
    __shared__ float Bn[BK][BN];

    const float* Ws = W;
    const float* Wn = W + (size_t)K * BN;
    const int tid = threadIdx.x;
    const int tx = tid % (BN / TN), ty = tid / (BN / TN);
    const int m0 = blockIdx.x * BM;

    float accS[TM][TN], accN[TM][TN];
#pragma unroll
    for (int i = 0; i < TM; i++)
#pragma unroll
        for (int j = 0; j < TN; j++) { accS[i][j] = 0.f; accN[i][j] = 0.f; }

    float4 ra, rs[BF4], rn[BF4];
    const int nkt = K / BK;

    {
        int row = tid >> 3, k4 = tid & 7;
        ra = *reinterpret_cast<const float4*>(A + (size_t)(m0 + row) * K + k4 * 4);
    }
#pragma unroll
    for (int u = 0; u < BF4; u++) {
        int id = tid + u * NT, row = id / (BN / 4), c4 = id % (BN / 4);
        rs[u] = *reinterpret_cast<const float4*>(Ws + (size_t)row * BN + c4 * 4);
        rn[u] = *reinterpret_cast<const float4*>(Wn + (size_t)row * BN + c4 * 4);
    }

    for (int kt = 0; kt < nkt; ++kt) {
        {
            int row = tid >> 3, k4 = tid & 7;
            As[k4 * 4 + 0][row] = ra.x; As[k4 * 4 + 1][row] = ra.y;
            As[k4 * 4 + 2][row] = ra.z; As[k4 * 4 + 3][row] = ra.w;
        }
#pragma unroll
        for (int u = 0; u < BF4; u++) {
            int id = tid + u * NT, row = id / (BN / 4), c4 = id % (BN / 4);
            *reinterpret_cast<float4*>(&Bs[row][c4 * 4]) = rs[u];
            *reinterpret_cast<float4*>(&Bn[row][c4 * 4]) = rn[u];
        }
        __syncthreads();
        if (kt + 1 < nkt) {
            const int kb = (kt + 1) * BK;
            {
                int row = tid >> 3, k4 = tid & 7;
                ra = *reinterpret_cast<const float4*>(
                    A + (size_t)(m0 + row) * K + kb + k4 * 4);
            }
#pragma unroll
            for (int u = 0; u < BF4; u++) {
                int id = tid + u * NT, row = id / (BN / 4), c4 = id % (BN / 4);
                rs[u] = *reinterpret_cast<const float4*>(
                    Ws + (size_t)(kb + row) * BN + c4 * 4);
                rn[u] = *reinterpret_cast<const float4*>(
                    Wn + (size_t)(kb + row) * BN + c4 * 4);
            }
        }
#pragma unroll
        for (int k = 0; k < BK; k++) {
            float a0 = As[k][ty * TM], a1 = As[k][ty * TM + 1];
            float bs[TN], bn[TN];
#pragma unroll
            for (int j = 0; j < TN; j += 4) {
                *reinterpret_cast<float4*>(bs + j) =
                    *reinterpret_cast<const float4*>(&Bs[k][tx * TN + j]);
                *reinterpret_cast<float4*>(bn + j) =
                    *reinterpret_cast<const float4*>(&Bn[k][tx * TN + j]);
            }
#pragma unroll
            for (int j = 0; j < TN; j++) {
                accS[0][j] = fmaf(a0, bs[j], accS[0][j]);
                accS[1][j] = fmaf(a1, bs[j], accS[1][j]);
                accN[0][j] = fmaf(a0, bn[j], accN[0][j]);
                accN[1][j] = fmaf(a1, bn[j], accN[1][j]);
            }
        }
        __syncthreads();
    }

#pragma unroll
    for (int i = 0; i < TM; i++) {
        const int row = m0 + ty * TM + i;
#pragma unroll
        for (int j = 0; j < TN; j += 4) {
            const int col = tx * TN + j;
            float4 v = make_float4(accS[i][j], accS[i][j+1], accS[i][j+2], accS[i][j+3]);
            float4 c = *reinterpret_cast<const float4*>(bias + col);
            v.x += c.x; v.y += c.y; v.z += c.z; v.w += c.w;
            *reinterpret_cast<float4*>(yout + (size_t)row * BN + col) = v;
        }
#pragma unroll
        for (int j = 0; j < TN; j += 2) {
            const int col = tx * TN + j;
            *reinterpret_cast<uint32_t*>(zh + (size_t)row * BN + col) =
                packh2(accN[i][j], accN[i][j + 1]);
        }
    }
}

extern "C" void kernel_launch(void* const* d_in, const int* in_sizes, int n_in,
                              void* d_out, int out_size)
{
    const float* x   = (const float*)d_in[0];
    const float* adj = (const float*)d_in[1];
    const float* W1  = (const float*)d_in[2];
    const float* b1  = (const float*)d_in[3];
    const float* W2  = (const float*)d_in[4];
    const float* b2  = (const float*)d_in[5];
    const float* W3  = (const float*)d_in[6];
    const float* b3  = (const float*)d_in[7];
    const float* W4  = (const float*)d_in[8];
    const float* b4  = (const float*)d_in[9];
    float* out = (float*)d_out;

    float *y, *h1, *h2;
    __half *zh, *adjh;
    cudaGetSymbolAddress((void**)&y,    g_y);
    cudaGetSymbolAddress((void**)&h1,   g_h1);
    cudaGetSymbolAddress((void**)&h2,   g_h2);
    cudaGetSymbolAddress((void**)&zh,   g_zh);
    cudaGetSymbolAddress((void**)&adjh, g_adjh);

    // smem: A 2 stages + B 3 stages (identical to R10)
    constexpr int SM128 = 2 * (64 * 144) + 3 * (64 * (128 * 2 + 16)); // 70656
    constexpr int SM64  = 2 * (64 * 144) + 3 * (64 * (64 * 2 + 16));  // 46080
    cudaFuncSetAttribute(agg_k<128, true>,  cudaFuncAttributeMaxDynamicSharedMemorySize, SM128);
    cudaFuncSetAttribute(agg_k<128, false>, cudaFuncAttributeMaxDynamicSharedMemorySize, SM128);
    cudaFuncSetAttribute(agg_k<64,  false>, cudaFuncAttributeMaxDynamicSharedMemorySize, SM64);

    const dim3 pg(MROWS / 32);
    const dim3 ag(MROWS / 64);

    proj_k<128><<<pg, 256>>>(x, W1, b1, y, zh, 256);
    agg_k<128, true ><<<ag, 512, SM128>>>(adj, adjh, zh, y, h1, 1);

    proj_k<128><<<pg, 256>>>(h1, W2, b2, y, zh, 128);
    agg_k<128, false><<<ag, 512, SM128>>>(nullptr, adjh, zh, y, h2, 1);

    proj_k<128><<<pg, 256>>>(h2, W3, b3, y, zh, 128);
    agg_k<128, false><<<ag, 512, SM128>>>(nullptr, adjh, zh, y, h1, 1);

    proj_k<64><<<pg, 256>>>(h1, W4, b4, y, zh, 128);
    agg_k<64,  false><<<ag, 512, SM64>>>(nullptr, adjh, zh, y, out, 0);
}

// round 13
// speedup vs baseline: 1.1219x; 1.1219x over previous
#include <cuda_runtime.h>
#include <cuda_fp16.h>
#include <stdint.h>

// GraphSAGE 4-layer, dense adj. N=8192, F: 256->128->128->64.
// h = act( h@W_self + adj @ (h@W_neigh) + b ).
// R13: 1-term fp16 agg (adj*4096 fp16 cached in g_adjh by layer 1).
// Agg: 4-way split-K warps (16 warps, warp tile 32 x BN/2, 1 kstep/warp),
// R12 skeleton (2-stage A reg-prefetch+STS, 3-stage cp.async B ring).
// Proj: fused self+neigh on the R6-proven BM=64/TM=4 tile.

static constexpr int MROWS = 8192;
static constexpr float A_SCALE = 4096.0f;
static constexpr float A_INV   = 1.0f / 4096.0f;

__device__ float g_y [8192 * 128];
__device__ float g_h1[8192 * 128];
__device__ float g_h2[8192 * 128];
__device__ __half g_zh[8192 * 128];
__device__ __half g_adjh[(size_t)8192 * 8192];

__device__ __forceinline__ uint32_t smem_u32(const void* p) {
    uint32_t a;
    asm("{ .reg .u64 t; cvta.to.shared.u64 t, %1; cvt.u32.u64 %0, t; }"
        : "=r"(a) : "l"(p));
    return a;
}
__device__ __forceinline__ uint32_t packh2(float a, float b) {
    __half2 t = __floats2half2_rn(a, b);
    return *reinterpret_cast<uint32_t*>(&t);
}
__device__ __forceinline__ void ldsm_x4(uint32_t* r, uint32_t addr) {
    asm volatile("ldmatrix.sync.aligned.m8n8.x4.shared.b16 {%0,%1,%2,%3}, [%4];"
                 : "=r"(r[0]), "=r"(r[1]), "=r"(r[2]), "=r"(r[3]) : "r"(addr));
}
__device__ __forceinline__ void ldsm_x4_t(uint32_t* r, uint32_t addr) {
    asm volatile("ldmatrix.sync.aligned.m8n8.x4.trans.shared.b16 {%0,%1,%2,%3}, [%4];"
                 : "=r"(r[0]), "=r"(r[1]), "=r"(r[2]), "=r"(r[3]) : "r"(addr));
}
__device__ __forceinline__ void mma_f16(float* d, const uint32_t* a,
                                        uint32_t b0, uint32_t b1) {
    asm volatile(
        "mma.sync.aligned.m16n8k16.row.col.f32.f16.f16.f32 "
        "{%0,%1,%2,%3}, {%4,%5,%6,%7}, {%8,%9}, {%0,%1,%2,%3};"
        : "+f"(d[0]), "+f"(d[1]), "+f"(d[2]), "+f"(d[3])
        : "r"(a[0]), "r"(a[1]), "r"(a[2]), "r"(a[3]), "r"(b0), "r"(b1));
}
__device__ __forceinline__ void cp16(uint32_t dst, const void* src) {
    asm volatile("cp.async.ca.shared.global [%0], [%1], 16;" :: "r"(dst), "l"(src));
}
#define CP_COMMIT() asm volatile("cp.async.commit_group;" ::: "memory")
#define CP_WAIT1()  asm volatile("cp.async.wait_group 1;" ::: "memory")

// ── aggregation: out = act(adj @ z + y); 512 threads, 4-way split-K ──
template <int BN, bool CVT>
__global__ __launch_bounds__(512) void agg_k(
    const float* __restrict__ adjf,
    __half* __restrict__ adjh,
    const __half* __restrict__ zh,
    const float* __restrict__ y,
    float* __restrict__ out,
    int relu)
{
    constexpr int NT = 512;
    constexpr int BM = 64, BK = 64, NCH = MROWS / BK;
    constexpr int LDA = 144;
    constexpr int ATILE = BM * LDA;
    constexpr int LDB = BN * 2 + 16;
    constexpr int BTILE = BK * LDB;
    constexpr int BOFF = 2 * ATILE;
    constexpr int CW = BN / 2;                     // warp col span (64 / 32)
    constexpr int NTN = CW / 8;                    // 8 / 4
    constexpr int NBL = NTN / 2;                   // 4 / 2
    constexpr int NCPB = BK * BN * 2 / 16;
    constexpr int BCP = (NCPB + NT - 1) / NT;
    constexpr int CPRB = BN / 8;

    extern __shared__ __align__(128) char sm[];
    const uint32_t smb = smem_u32(sm);
    const int tid = threadIdx.x, m0 = blockIdx.x * BM;
    const int w = tid >> 5, lane = tid & 31;
    const int kw = w >> 2, wi = w & 3;             // k-quarter, tile id
    const int wr = wi >> 1, wc = wi & 1;           // 2 row x 2 col warp tiles

    float acc[2][NTN][4];
#pragma unroll
    for (int mt = 0; mt < 2; mt++)
#pragma unroll
        for (int nt = 0; nt < NTN; nt++)
#pragma unroll
            for (int q = 0; q < 4; q++) acc[mt][nt][q] = 0.f;

    float4 raf[2];
    uint4  rah;

    auto prefA = [&](int chunk) {
        const size_t kb = (size_t)chunk * BK;
        if (CVT) {
#pragma unroll
            for (int u = 0; u < 2; u++) {
                int id = tid + u * NT, row = id >> 4, c = id & 15;
                raf[u] = *reinterpret_cast<const float4*>(
                    adjf + (size_t)(m0 + row) * MROWS + kb + c * 4);
            }
        } else {
            int row = tid >> 3, c = tid & 7;
            rah = *reinterpret_cast<const uint4*>(
                adjh + (size_t)(m0 + row) * MROWS + kb + c * 8);
        }
    };
    auto commitA = [&](int sa, int chunk) {
        const size_t kb = (size_t)chunk * BK;
        if (CVT) {
#pragma unroll
            for (int u = 0; u < 2; u++) {
                int id = tid + u * NT, row = id >> 4, c = id & 15;
                uint32_t h01 = packh2(raf[u].x * A_SCALE, raf[u].y * A_SCALE);
                uint32_t h23 = packh2(raf[u].z * A_SCALE, raf[u].w * A_SCALE);
                uint32_t off = (uint32_t)(row * LDA + c * 8);
                *reinterpret_cast<uint2*>(sm + sa * ATILE + off) =
                    make_uint2(h01, h23);
                *reinterpret_cast<uint2*>(
                    adjh + (size_t)(m0 + row) * MROWS + kb + c * 4) =
                    make_uint2(h01, h23);
            }
        } else {
            int row = tid >> 3, c = tid & 7;
            *reinterpret_cast<uint4*>(sm + sa * ATILE + row * LDA + c * 16) = rah;
        }
    };
    auto issueB = [&](int chunk) {
        const uint32_t base = smb + BOFF + (chunk % 3) * BTILE;
        const size_t kb = (size_t)chunk * BK;
#pragma unroll
        for (int u = 0; u < BCP; u++) {
            int id = tid + u * NT;
            if (NCPB % NT == 0 || id < NCPB) {
                int krow = id / CPRB, c = id % CPRB;
                cp16(base + (uint32_t)(krow * LDB + c * 16),
                     zh + (kb + krow) * BN + c * 8);
            }
        }
    };

    const uint32_t a_lrow =
        (uint32_t)(wr * 32 + (lane & 15)) * LDA + (lane >> 4) * 16;

    auto compute = [&](int sa, int sb) {
        const uint32_t ab = smb + sa * ATILE;
        const uint32_t bb = smb + BOFF + sb * BTILE;
        const int ks = kw;                         // one kstep per warp
        uint32_t ah[2][4];
#pragma unroll
        for (int mt = 0; mt < 2; mt++)
            ldsm_x4(ah[mt], ab + a_lrow + mt * (16 * LDA) + ks * 32);
        uint32_t zb[NBL][4];
#pragma unroll
        for (int bt = 0; bt < NBL; bt++) {
            int krow = ks * 16 + (lane & 15);
            int ncol = wc * CW + bt * 16 + (lane >> 4) * 8;
            ldsm_x4_t(zb[bt], bb + (uint32_t)(krow * LDB + ncol * 2));
        }
#pragma unroll
        for (int mt = 0; mt < 2; mt++)
#pragma unroll
            for (int nt = 0; nt < NTN; nt++) {
                const int g = nt >> 1, p = (nt & 1) * 2;
                mma_f16(acc[mt][nt], ah[mt], zb[g][p], zb[g][p + 1]);
            }
    };

    issueB(0); CP_COMMIT();
    issueB(1); CP_COMMIT();
    prefA(0);
    commitA(0, 0);
    prefA(1);

    for (int i = 0; i < NCH; i++) {
        const int sa = i & 1, sb = i % 3;
        CP_WAIT1();
        __syncthreads();
        compute(sa, sb);
        if (i + 2 < NCH) { issueB(i + 2); CP_COMMIT(); }
        if (i + 1 < NCH) {
            commitA((i + 1) & 1, i + 1);
            if (i + 2 < NCH) prefA(i + 2);
        }
    }

    // merge k-quarters: 3 publish rounds into smem, kw==0 accumulates
    __syncthreads();
    float* ps = reinterpret_cast<float*>(sm);
#pragma unroll 1
    for (int p = 1; p < 4; p++) {
        if (kw == p) {
#pragma unroll
            for (int mt = 0; mt < 2; mt++)
#pragma unroll
                for (int nt = 0; nt < NTN; nt++)
#pragma unroll
                    for (int q = 0; q < 4; q++)
                        ps[((((wi * 2 + mt) * NTN + nt) * 4) + q) * 32 + lane] =
                            acc[mt][nt][q];
        }
        __syncthreads();
        if (kw == 0) {
#pragma unroll
            for (int mt = 0; mt < 2; mt++)
#pragma unroll
                for (int nt = 0; nt < NTN; nt++)
#pragma unroll
                    for (int q = 0; q < 4; q++)
                        acc[mt][nt][q] +=
                            ps[((((wi * 2 + mt) * NTN + nt) * 4) + q) * 32 + lane];
        }
        __syncthreads();
    }
    if (kw == 0) {
        const int g = lane >> 2, cp2 = (lane & 3) * 2;
#pragma unroll
        for (int mt = 0; mt < 2; mt++) {
            const int r0 = m0 + wr * 32 + mt * 16 + g;
#pragma unroll
            for (int nt = 0; nt < NTN; nt++) {
                const int col = wc * CW + nt * 8 + cp2;
#pragma unroll
                for (int half = 0; half < 2; half++) {
                    const size_t row = (size_t)(r0 + half * 8);
                    float2 yv = *reinterpret_cast<const float2*>(y + row * BN + col);
                    float v0 = acc[mt][nt][2 * half + 0] * A_INV + yv.x;
                    float v1 = acc[mt][nt][2 * half + 1] * A_INV + yv.y;
                    if (relu) { v0 = fmaxf(v0, 0.f); v1 = fmaxf(v1, 0.f); }
                    *reinterpret_cast<float2*>(out + row * BN + col) =
                        make_float2(v0, v1);
                }
            }
        }
    }
}

// ── fused projection (R6 tile): y = A@W[0:K]+b ; z = A@W[K:2K] -> fp16 ──
// BM=64, BK=16, TM=4, TN=8.
template <int BN, int NT>
__global__ __launch_bounds__(NT) void proj_k(
    const float* __restrict__ A,
    const float* __restrict__ W,
    const float* __restrict__ bias,
    float* __restrict__ yout,
    __half* __restrict__ zh,
    int K)
{
    constexpr int BM = 64, BK = 16, TM = 4, TN = 8;
    constexpr int AF4 = (BM * BK / 4) / NT;
    constexpr int BF4 = (BK * BN / 4) / NT;
    __shared__ float As[BK][BM];
    __shared__ float Bs[BK][BN];
    __shared__ float Bn[BK][BN];

    const float* Ws = W;
    const float* Wn = W + (size_t)K * BN;
    const int tid = threadIdx.x;
    const int tx = tid % (BN / TN), ty = tid / (BN / TN);
    const int m0 = blockIdx.x * BM;

    float accS[TM][TN], accN[TM][TN];
#pragma unroll
    for (int i = 0; i < TM; i++)
#pragma unroll
        for (int j = 0; j < TN; j++) { accS[i][j] = 0.f; accN[i][j] = 0.f; }

    float4 ra[AF4], rs[BF4], rn[BF4];
    const int nkt = K / BK;

#pragma unroll
    for (int u = 0; u < AF4; u++) {
        int id = tid + u * NT, row = id >> 2, k4 = id & 3;
        ra[u] = *reinterpret_cast<const float4*>(A + (size_t)(m0 + row) * K + k4 * 4);
    }
#pragma unroll
    for (int u = 0; u < BF4; u++) {
        int id = tid + u * NT, row = id / (BN / 4), c4 = id % (BN / 4);
        rs[u] = *reinterpret_cast<const float4*>(Ws + (size_t)row * BN + c4 * 4);
        rn[u] = *reinterpret_cast<const float4*>(Wn + (size_t)row * BN + c4 * 4);
    }
    for (int kt = 0; kt < nkt; ++kt) {
#pragma unroll
        for (int u = 0; u < AF4; u++) {
            int id = tid + u * NT, row = id >> 2, k4 = id & 3;
            As[k4 * 4 + 0][row] = ra[u].x; As[k4 * 4 + 1][row] = ra[u].y;
            As[k4 * 4 + 2][row] = ra[u].z; As[k4 * 4 + 3][row] = ra[u].w;
        }
#pragma unroll
        for (int u = 0; u < BF4; u++) {
            int id = tid + u * NT, row = id / (BN / 4), c4 = id % (BN / 4);
            *reinterpret_cast<float4*>(&Bs[row][c4 * 4]) = rs[u];
            *reinterpret_cast<float4*>(&Bn[row][c4 * 4]) = rn[u];
        }
        __syncthreads();
        if (kt + 1 < nkt) {
            const int kb = (kt + 1) * BK;
#pragma unroll
            for (int u = 0; u < AF4; u++) {
                int id = tid + u * NT, row = id >> 2, k4 = id & 3;
                ra[u] = *reinterpret_cast<const float4*>(
                    A + (size_t)(m0 + row) * K + kb + k4 * 4);
            }
#pragma unroll
            for (int u = 0; u < BF4; u++) {
                int id = tid + u * NT, row = id / (BN / 4), c4 = id % (BN / 4);
                rs[u] = *reinterpret_cast<const float4*>(
                    Ws + (size_t)(kb + row) * BN + c4 * 4);
                rn[u] = *reinterpret_cast<const float4*>(
                    Wn + (size_t)(kb + row) * BN + c4 * 4);
            }
        }
#pragma unroll
        for (int k = 0; k < BK; k++) {
            float a[TM], bs[TN], bn[TN];
            *reinterpret_cast<float4*>(a) =
                *reinterpret_cast<const float4*>(&As[k][ty * TM]);
            *reinterpret_cast<float4*>(bs) =
                *reinterpret_cast<const float4*>(&Bs[k][tx * TN]);
            *reinterpret_cast<float4*>(bs + 4) =
                *reinterpret_cast<const float4*>(&Bs[k][tx * TN + 4]);
            *reinterpret_cast<float4*>(bn) =
                *reinterpret_cast<const float4*>(&Bn[k][tx * TN]);
            *reinterpret_cast<float4*>(bn + 4) =
                *reinterpret_cast<const float4*>(&Bn[k][tx * TN + 4]);
#pragma unroll
            for (int i = 0; i < TM; i++)
#pragma unroll
                for (int j = 0; j < TN; j++) {
                    accS[i][j] = fmaf(a[i], bs[j], accS[i][j]);
                    accN[i][j] = fmaf(a[i], bn[j], accN[i][j]);
                }
        }
        __syncthreads();
    }
#pragma unroll
    for (int i = 0; i < TM; i++) {
        const int row = m0 + ty * TM + i;
#pragma unroll
        for (int j = 0; j < TN; j += 4) {
            const int col = tx * TN + j;
            float4 v = make_float4(accS[i][j], accS[i][j+1], accS[i][j+2], accS[i][j+3]);
            float4 c = *reinterpret_cast<const float4*>(bias + col);
            v.x += c.x; v.y += c.y; v.z += c.z; v.w += c.w;
            *reinterpret_cast<float4*>(yout + (size_t)row * BN + col) = v;
        }
#pragma unroll
        for (int j = 0; j < TN; j += 2) {
            const int col = tx * TN + j;
            *reinterpret_cast<uint32_t*>(zh + (size_t)row * BN + col) =
                packh2(accN[i][j], accN[i][j + 1]);
        }
    }
}

extern "C" void kernel_launch(void* const* d_in, const int* in_sizes, int n_in,
                              void* d_out, int out_size)
{
    const float* x   = (const float*)d_in[0];
    const float* adj = (const float*)d_in[1];
    const float* W1  = (const float*)d_in[2];
    const float* b1  = (const float*)d_in[3];
    const float* W2  = (const float*)d_in[4];
    const float* b2  = (const float*)d_in[5];
    const float* W3  = (const float*)d_in[6];
    const float* b3  = (const float*)d_in[7];
    const float* W4  = (const float*)d_in[8];
    const float* b4  = (const float*)d_in[9];
    float* out = (float*)d_out;

    float *y, *h1, *h2;
    __half *zh, *adjh;
    cudaGetSymbolAddress((void**)&y,    g_y);
    cudaGetSymbolAddress((void**)&h1,   g_h1);
    cudaGetSymbolAddress((void**)&h2,   g_h2);
    cudaGetSymbolAddress((void**)&zh,   g_zh);
    cudaGetSymbolAddress((void**)&adjh, g_adjh);

    constexpr int SM128 = 2 * (64 * 144) + 3 * (64 * (128 * 2 + 16)); // 70656
    constexpr int SM64  = 2 * (64 * 144) + 3 * (64 * (64 * 2 + 16));  // 46080
    cudaFuncSetAttribute(agg_k<128, true>,  cudaFuncAttributeMaxDynamicSharedMemorySize, SM128);
    cudaFuncSetAttribute(agg_k<128, false>, cudaFuncAttributeMaxDynamicSharedMemorySize, SM128);
    cudaFuncSetAttribute(agg_k<64,  false>, cudaFuncAttributeMaxDynamicSharedMemorySize, SM64);

    const dim3 pg(MROWS / 64);
    const dim3 ag(MROWS / 64);

    proj_k<128, 256><<<pg, 256>>>(x, W1, b1, y, zh, 256);
    agg_k<128, true ><<<ag, 512, SM128>>>(adj, adjh, zh, y, h1, 1);

    proj_k<128, 256><<<pg, 256>>>(h1, W2, b2, y, zh, 128);
    agg_k<128, false><<<ag, 512, SM128>>>(nullptr, adjh, zh, y, h2, 1);

    proj_k<128, 256><<<pg, 256>>>(h2, W3, b3, y, zh, 128);
    agg_k<128, false><<<ag, 512, SM128>>>(nullptr, adjh, zh, y, h1, 1);

    proj_k<64, 128><<<pg, 128>>>(h1, W4, b4, y, zh, 128);
    agg_k<64,  false><<<ag, 512, SM64>>>(nullptr, adjh, zh, y, out, 0);
}

// round 14
// speedup vs baseline: 1.4349x; 1.2791x over previous
#include <cuda_runtime.h>
#include <cuda_fp16.h>
#include <stdint.h>

// GraphSAGE 4-layer, dense adj. N=8192, F: 256->128->128->64.
// h = act( h@W_self + adj @ (h@W_neigh) + b ).
// R14: BK=128 chunks (64 iterations, half the barriers), cp.async.cg for B.
// 1-term fp16 agg (adj*4096 fp16 cached in g_adjh by layer 1), 4-way
// split-K warps (2 ksteps/warp/chunk), 2-stage A reg-prefetch+STS,
// 3-stage cp.async B ring, smem k-merge. Proj: fused BM=64/TM=4 tile.

static constexpr int MROWS = 8192;
static constexpr float A_SCALE = 4096.0f;
static constexpr float A_INV   = 1.0f / 4096.0f;

__device__ float g_y [8192 * 128];
__device__ float g_h1[8192 * 128];
__device__ float g_h2[8192 * 128];
__device__ __half g_zh[8192 * 128];
__device__ __half g_adjh[(size_t)8192 * 8192];

__device__ __forceinline__ uint32_t smem_u32(const void* p) {
    uint32_t a;
    asm("{ .reg .u64 t; cvta.to.shared.u64 t, %1; cvt.u32.u64 %0, t; }"
        : "=r"(a) : "l"(p));
    return a;
}
__device__ __forceinline__ uint32_t packh2(float a, float b) {
    __half2 t = __floats2half2_rn(a, b);
    return *reinterpret_cast<uint32_t*>(&t);
}
__device__ __forceinline__ void ldsm_x4(uint32_t* r, uint32_t addr) {
    asm volatile("ldmatrix.sync.aligned.m8n8.x4.shared.b16 {%0,%1,%2,%3}, [%4];"
                 : "=r"(r[0]), "=r"(r[1]), "=r"(r[2]), "=r"(r[3]) : "r"(addr));
}
__device__ __forceinline__ void ldsm_x4_t(uint32_t* r, uint32_t addr) {
    asm volatile("ldmatrix.sync.aligned.m8n8.x4.trans.shared.b16 {%0,%1,%2,%3}, [%4];"
                 : "=r"(r[0]), "=r"(r[1]), "=r"(r[2]), "=r"(r[3]) : "r"(addr));
}
__device__ __forceinline__ void mma_f16(float* d, const uint32_t* a,
                                        uint32_t b0, uint32_t b1) {
    asm volatile(
        "mma.sync.aligned.m16n8k16.row.col.f32.f16.f16.f32 "
        "{%0,%1,%2,%3}, {%4,%5,%6,%7}, {%8,%9}, {%0,%1,%2,%3};"
        : "+f"(d[0]), "+f"(d[1]), "+f"(d[2]), "+f"(d[3])
        : "r"(a[0]), "r"(a[1]), "r"(a[2]), "r"(a[3]), "r"(b0), "r"(b1));
}
__device__ __forceinline__ void cp16cg(uint32_t dst, const void* src) {
    asm volatile("cp.async.cg.shared.global [%0], [%1], 16;" :: "r"(dst), "l"(src));
}
#define CP_COMMIT() asm volatile("cp.async.commit_group;" ::: "memory")
#define CP_WAIT1()  asm volatile("cp.async.wait_group 1;" ::: "memory")

// ── aggregation: out = act(adj @ z + y); 512 threads, 4-way split-K, BK=128 ──
template <int BN, bool CVT>
__global__ __launch_bounds__(512) void agg_k(
    const float* __restrict__ adjf,
    __half* __restrict__ adjh,
    const __half* __restrict__ zh,
    const float* __restrict__ y,
    float* __restrict__ out,
    int relu)
{
    constexpr int NT = 512;
    constexpr int BM = 64, BK = 128, NCH = MROWS / BK;   // 64 chunks
    constexpr int LDA = 272;                       // 256B fp16 row + 16B pad
    constexpr int ATILE = BM * LDA;                // 17408
    constexpr int LDB = BN * 2 + 16;
    constexpr int BTILE = BK * LDB;
    constexpr int BOFF = 2 * ATILE;
    constexpr int CW = BN / 2;                     // warp col span (64 / 32)
    constexpr int NTN = CW / 8;                    // 8 / 4
    constexpr int NBL = NTN / 2;                   // 4 / 2
    constexpr int NCPB = BK * BN * 2 / 16;         // 2048 / 1024
    constexpr int BCP = NCPB / NT;                 // 4 / 2
    constexpr int CPRB = BN / 8;

    extern __shared__ __align__(128) char sm[];
    const uint32_t smb = smem_u32(sm);
    const int tid = threadIdx.x, m0 = blockIdx.x * BM;
    const int w = tid >> 5, lane = tid & 31;
    const int kw = w >> 2, wi = w & 3;
    const int wr = wi >> 1, wc = wi & 1;

    float acc[2][NTN][4];
#pragma unroll
    for (int mt = 0; mt < 2; mt++)
#pragma unroll
        for (int nt = 0; nt < NTN; nt++)
#pragma unroll
            for (int q = 0; q < 4; q++) acc[mt][nt][q] = 0.f;

    float4 raf[4];
    uint4  rah[2];

    auto prefA = [&](int chunk) {
        const size_t kb = (size_t)chunk * BK;
        if (CVT) {
#pragma unroll
            for (int u = 0; u < 4; u++) {
                int id = tid + u * NT, row = id >> 5, c = id & 31;
                raf[u] = *reinterpret_cast<const float4*>(
                    adjf + (size_t)(m0 + row) * MROWS + kb + c * 4);
            }
        } else {
#pragma unroll
            for (int u = 0; u < 2; u++) {
                int id = tid + u * NT, row = id >> 4, c = id & 15;
                rah[u] = *reinterpret_cast<const uint4*>(
                    adjh + (size_t)(m0 + row) * MROWS + kb + c * 8);
            }
        }
    };
    auto commitA = [&](int sa, int chunk) {
        const size_t kb = (size_t)chunk * BK;
        if (CVT) {
#pragma unroll
            for (int u = 0; u < 4; u++) {
                int id = tid + u * NT, row = id >> 5, c = id & 31;
                uint32_t h01 = packh2(raf[u].x * A_SCALE, raf[u].y * A_SCALE);
                uint32_t h23 = packh2(raf[u].z * A_SCALE, raf[u].w * A_SCALE);
                uint32_t off = (uint32_t)(row * LDA + c * 8);
                *reinterpret_cast<uint2*>(sm + sa * ATILE + off) =
                    make_uint2(h01, h23);
                *reinterpret_cast<uint2*>(
                    adjh + (size_t)(m0 + row) * MROWS + kb + c * 4) =
                    make_uint2(h01, h23);
            }
        } else {
#pragma unroll
            for (int u = 0; u < 2; u++) {
                int id = tid + u * NT, row = id >> 4, c = id & 15;
                *reinterpret_cast<uint4*>(sm + sa * ATILE + row * LDA + c * 16) =
                    rah[u];
            }
        }
    };
    auto issueB = [&](int chunk) {
        const uint32_t base = smb + BOFF + (chunk % 3) * BTILE;
        const size_t kb = (size_t)chunk * BK;
#pragma unroll
        for (int u = 0; u < BCP; u++) {
            int id = tid + u * NT;
            int krow = id / CPRB, c = id % CPRB;
            cp16cg(base + (uint32_t)(krow * LDB + c * 16),
                   zh + (kb + krow) * BN + c * 8);
        }
    };

    const uint32_t a_lrow =
        (uint32_t)(wr * 32 + (lane & 15)) * LDA + (lane >> 4) * 16;

    auto compute = [&](int sa, int sb) {
        const uint32_t ab = smb + sa * ATILE;
        const uint32_t bb = smb + BOFF + sb * BTILE;
#pragma unroll
        for (int s = 0; s < 2; s++) {
            const int ks = kw * 2 + s;             // 0..7
            uint32_t ah[2][4];
#pragma unroll
            for (int mt = 0; mt < 2; mt++)
                ldsm_x4(ah[mt], ab + a_lrow + mt * (16 * LDA) + ks * 32);
            uint32_t zb[NBL][4];
#pragma unroll
            for (int bt = 0; bt < NBL; bt++) {
                int krow = ks * 16 + (lane & 15);
                int ncol = wc * CW + bt * 16 + (lane >> 4) * 8;
                ldsm_x4_t(zb[bt], bb + (uint32_t)(krow * LDB + ncol * 2));
            }
#pragma unroll
            for (int mt = 0; mt < 2; mt++)
#pragma unroll
                for (int nt = 0; nt < NTN; nt++) {
                    const int g = nt >> 1, p = (nt & 1) * 2;
                    mma_f16(acc[mt][nt], ah[mt], zb[g][p], zb[g][p + 1]);
                }
        }
    };

    issueB(0); CP_COMMIT();
    issueB(1); CP_COMMIT();
    prefA(0);
    commitA(0, 0);
    prefA(1);

    for (int i = 0; i < NCH; i++) {
        const int sa = i & 1, sb = i % 3;
        CP_WAIT1();
        __syncthreads();
        compute(sa, sb);
        if (i + 2 < NCH) { issueB(i + 2); CP_COMMIT(); }
        if (i + 1 < NCH) {
            commitA((i + 1) & 1, i + 1);
            if (i + 2 < NCH) prefA(i + 2);
        }
    }

    // merge k-quarters
    __syncthreads();
    float* ps = reinterpret_cast<float*>(sm);
#pragma unroll 1
    for (int p = 1; p < 4; p++) {
        if (kw == p) {
#pragma unroll
            for (int mt = 0; mt < 2; mt++)
#pragma unroll
                for (int nt = 0; nt < NTN; nt++)
#pragma unroll
                    for (int q = 0; q < 4; q++)
                        ps[((((wi * 2 + mt) * NTN + nt) * 4) + q) * 32 + lane] =
                            acc[mt][nt][q];
        }
        __syncthreads();
        if (kw == 0) {
#pragma unroll
            for (int mt = 0; mt < 2; mt++)
#pragma unroll
                for (int nt = 0; nt < NTN; nt++)
#pragma unroll
                    for (int q = 0; q < 4; q++)
                        acc[mt][nt][q] +=
                            ps[((((wi * 2 + mt) * NTN + nt) * 4) + q) * 32 + lane];
        }
        __syncthreads();
    }
    if (kw == 0) {
        const int g = lane >> 2, cp2 = (lane & 3) * 2;
#pragma unroll
        for (int mt = 0; mt < 2; mt++) {
            const int r0 = m0 + wr * 32 + mt * 16 + g;
#pragma unroll
            for (int nt = 0; nt < NTN; nt++) {
                const int col = wc * CW + nt * 8 + cp2;
#pragma unroll
                for (int half = 0; half < 2; half++) {
                    const size_t row = (size_t)(r0 + half * 8);
                    float2 yv = *reinterpret_cast<const float2*>(y + row * BN + col);
                    float v0 = acc[mt][nt][2 * half + 0] * A_INV + yv.x;
                    float v1 = acc[mt][nt][2 * half + 1] * A_INV + yv.y;
                    if (relu) { v0 = fmaxf(v0, 0.f); v1 = fmaxf(v1, 0.f); }
                    *reinterpret_cast<float2*>(out + row * BN + col) =
                        make_float2(v0, v1);
                }
            }
        }
    }
}

// ── fused projection (R6 tile): y = A@W[0:K]+b ; z = A@W[K:2K] -> fp16 ──
template <int BN, int NT>
__global__ __launch_bounds__(NT) void proj_k(
    const float* __restrict__ A,
    const float* __restrict__ W,
    const float* __restrict__ bias,
    float* __restrict__ yout,
    __half* __restrict__ zh,
    int K)
{
    constexpr int BM = 64, BK = 16, TM = 4, TN = 8;
    constexpr int AF4 = (BM * BK / 4) / NT;
    constexpr int BF4 = (BK * BN / 4) / NT;
    __shared__ float As[BK][BM];
    __shared__ float Bs[BK][BN];
    __shared__ float Bn[BK][BN];

    const float* Ws = W;
    const float* Wn = W + (size_t)K * BN;
    const int tid = threadIdx.x;
    const int tx = tid % (BN / TN), ty = tid / (BN / TN);
    const int m0 = blockIdx.x * BM;

    float accS[TM][TN], accN[TM][TN];
#pragma unroll
    for (int i = 0; i < TM; i++)
#pragma unroll
        for (int j = 0; j < TN; j++) { accS[i][j] = 0.f; accN[i][j] = 0.f; }

    float4 ra[AF4], rs[BF4], rn[BF4];
    const int nkt = K / BK;

#pragma unroll
    for (int u = 0; u < AF4; u++) {
        int id = tid + u * NT, row = id >> 2, k4 = id & 3;
        ra[u] = *reinterpret_cast<const float4*>(A + (size_t)(m0 + row) * K + k4 * 4);
    }
#pragma unroll
    for (int u = 0; u < BF4; u++) {
        int id = tid + u * NT, row = id / (BN / 4), c4 = id % (BN / 4);
        rs[u] = *reinterpret_cast<const float4*>(Ws + (size_t)row * BN + c4 * 4);
        rn[u] = *reinterpret_cast<const float4*>(Wn + (size_t)row * BN + c4 * 4);
    }
    for (int kt = 0; kt < nkt; ++kt) {
#pragma unroll
        for (int u = 0; u < AF4; u++) {
            int id = tid + u * NT, row = id >> 2, k4 = id & 3;
            As[k4 * 4 + 0][row] = ra[u].x; As[k4 * 4 + 1][row] = ra[u].y;
            As[k4 * 4 + 2][row] = ra[u].z; As[k4 * 4 + 3][row] = ra[u].w;
        }
#pragma unroll
        for (int u = 0; u < BF4; u++) {
            int id = tid + u * NT, row = id / (BN / 4), c4 = id % (BN / 4);
            *reinterpret_cast<float4*>(&Bs[row][c4 * 4]) = rs[u];
            *reinterpret_cast<float4*>(&Bn[row][c4 * 4]) = rn[u];
        }
        __syncthreads();
        if (kt + 1 < nkt) {
            const int kb = (kt + 1) * BK;
#pragma unroll
            for (int u = 0; u < AF4; u++) {
                int id = tid + u * NT, row = id >> 2, k4 = id & 3;
                ra[u] = *reinterpret_cast<const float4*>(
                    A + (size_t)(m0 + row) * K + kb + k4 * 4);
            }
#pragma unroll
            for (int u = 0; u < BF4; u++) {
                int id = tid + u * NT, row = id / (BN / 4), c4 = id % (BN / 4);
                rs[u] = *reinterpret_cast<const float4*>(
                    Ws + (size_t)(kb + row) * BN + c4 * 4);
                rn[u] = *reinterpret_cast<const float4*>(
                    Wn + (size_t)(kb + row) * BN + c4 * 4);
            }
        }
#pragma unroll
        for (int k = 0; k < BK; k++) {
            float a[TM], bs[TN], bn[TN];
            *reinterpret_cast<float4*>(a) =
                *reinterpret_cast<const float4*>(&As[k][ty * TM]);
            *reinterpret_cast<float4*>(bs) =
                *reinterpret_cast<const float4*>(&Bs[k][tx * TN]);
            *reinterpret_cast<float4*>(bs + 4) =
                *reinterpret_cast<const float4*>(&Bs[k][tx * TN + 4]);
            *reinterpret_cast<float4*>(bn) =
                *reinterpret_cast<const float4*>(&Bn[k][tx * TN]);
            *reinterpret_cast<float4*>(bn + 4) =
                *reinterpret_cast<const float4*>(&Bn[k][tx * TN + 4]);
#pragma unroll
            for (int i = 0; i < TM; i++)
#pragma unroll
                for (int j = 0; j < TN; j++) {
                    accS[i][j] = fmaf(a[i], bs[j], accS[i][j]);
                    accN[i][j] = fmaf(a[i], bn[j], accN[i][j]);
                }
        }
        __syncthreads();
    }
#pragma unroll
    for (int i = 0; i < TM; i++) {
        const int row = m0 + ty * TM + i;
#pragma unroll
        for (int j = 0; j < TN; j += 4) {
            const int col = tx * TN + j;
            float4 v = make_float4(accS[i][j], accS[i][j+1], accS[i][j+2], accS[i][j+3]);
            float4 c = *reinterpret_cast<const float4*>(bias + col);
            v.x += c.x; v.y += c.y; v.z += c.z; v.w += c.w;
            *reinterpret_cast<float4*>(yout + (size_t)row * BN + col) = v;
        }
#pragma unroll
        for (int j = 0; j < TN; j += 2) {
            const int col = tx * TN + j;
            *reinterpret_cast<uint32_t*>(zh + (size_t)row * BN + col) =
                packh2(accN[i][j], accN[i][j + 1]);
        }
    }
}

extern "C" void kernel_launch(void* const* d_in, const int* in_sizes, int n_in,
                              void* d_out, int out_size)
{
    const float* x   = (const float*)d_in[0];
    const float* adj = (const float*)d_in[1];
    const float* W1  = (const float*)d_in[2];
    const float* b1  = (const float*)d_in[3];
    const float* W2  = (const float*)d_in[4];
    const float* b2  = (const float*)d_in[5];
    const float* W3  = (const float*)d_in[6];
    const float* b3  = (const float*)d_in[7];
    const float* W4  = (const float*)d_in[8];
    const float* b4  = (const float*)d_in[9];
    float* out = (float*)d_out;

    float *y, *h1, *h2;
    __half *zh, *adjh;
    cudaGetSymbolAddress((void**)&y,    g_y);
    cudaGetSymbolAddress((void**)&h1,   g_h1);
    cudaGetSymbolAddress((void**)&h2,   g_h2);
    cudaGetSymbolAddress((void**)&zh,   g_zh);
    cudaGetSymbolAddress((void**)&adjh, g_adjh);

    // smem: A 2 stages (64x272) + B 3 stages (128 x (BN*2+16))
    constexpr int SM128 = 2 * (64 * 272) + 3 * (128 * (128 * 2 + 16)); // 139264
    constexpr int SM64  = 2 * (64 * 272) + 3 * (128 * (64 * 2 + 16));  //  90112
    cudaFuncSetAttribute(agg_k<128, true>,  cudaFuncAttributeMaxDynamicSharedMemorySize, SM128);
    cudaFuncSetAttribute(agg_k<128, false>, cudaFuncAttributeMaxDynamicSharedMemorySize, SM128);
    cudaFuncSetAttribute(agg_k<64,  false>, cudaFuncAttributeMaxDynamicSharedMemorySize, SM64);

    const dim3 pg(MROWS / 64);
    const dim3 ag(MROWS / 64);

    proj_k<128, 256><<<pg, 256>>>(x, W1, b1, y, zh, 256);
    agg_k<128, true ><<<ag, 512, SM128>>>(adj, adjh, zh, y, h1, 1);

    proj_k<128, 256><<<pg, 256>>>(h1, W2, b2, y, zh, 128);
    agg_k<128, false><<<ag, 512, SM128>>>(nullptr, adjh, zh, y, h2, 1);

    proj_k<128, 256><<<pg, 256>>>(h2, W3, b3, y, zh, 128);
    agg_k<128, false><<<ag, 512, SM128>>>(nullptr, adjh, zh, y, h1, 1);

    proj_k<64, 128><<<pg, 128>>>(h1, W4, b4, y, zh, 128);
    agg_k<64,  false><<<ag, 512, SM64>>>(nullptr, adjh, zh, y, out, 0);
}

// round 15
// speedup vs baseline: 1.6024x; 1.1167x over previous
#include <cuda_runtime.h>
#include <cuda_fp16.h>
#include <stdint.h>

// GraphSAGE 4-layer, dense adj. N=8192, F: 256->128->128->64.
// h = act( h@W_self + adj @ (h@W_neigh) + b ).
// R15: aggregation as R14 (BK=128, 4-way split-K, cp.async.cg B ring) but
// epilogue writes h in fp16 (layers 1-3). Projections 2-4 are single-shot
// fp16 MMA kernels (K=128: one tile, one barrier); W2-4 pre-converted fp16.
// Layer-1 projection stays SIMT fp32 (x input).

static constexpr int MROWS = 8192;
static constexpr float A_SCALE = 4096.0f;
static constexpr float A_INV   = 1.0f / 4096.0f;

__device__ float g_y [8192 * 128];
__device__ __align__(16) __half g_zh[8192 * 128];
__device__ __align__(16) __half g_hh[8192 * 128];
__device__ __align__(16) __half g_adjh[(size_t)8192 * 8192];
__device__ __align__(16) __half g_w2h[256 * 128];
__device__ __align__(16) __half g_w3h[256 * 128];
__device__ __align__(16) __half g_w4h[256 * 64];

__device__ __forceinline__ uint32_t smem_u32(const void* p) {
    uint32_t a;
    asm("{ .reg .u64 t; cvta.to.shared.u64 t, %1; cvt.u32.u64 %0, t; }"
        : "=r"(a) : "l"(p));
    return a;
}
__device__ __forceinline__ uint32_t packh2(float a, float b) {
    __half2 t = __floats2half2_rn(a, b);
    return *reinterpret_cast<uint32_t*>(&t);
}
__device__ __forceinline__ void ldsm_x4(uint32_t* r, uint32_t addr) {
    asm volatile("ldmatrix.sync.aligned.m8n8.x4.shared.b16 {%0,%1,%2,%3}, [%4];"
                 : "=r"(r[0]), "=r"(r[1]), "=r"(r[2]), "=r"(r[3]) : "r"(addr));
}
__device__ __forceinline__ void ldsm_x4_t(uint32_t* r, uint32_t addr) {
    asm volatile("ldmatrix.sync.aligned.m8n8.x4.trans.shared.b16 {%0,%1,%2,%3}, [%4];"
                 : "=r"(r[0]), "=r"(r[1]), "=r"(r[2]), "=r"(r[3]) : "r"(addr));
}
__device__ __forceinline__ void mma_f16(float* d, const uint32_t* a,
                                        uint32_t b0, uint32_t b1) {
    asm volatile(
        "mma.sync.aligned.m16n8k16.row.col.f32.f16.f16.f32 "
        "{%0,%1,%2,%3}, {%4,%5,%6,%7}, {%8,%9}, {%0,%1,%2,%3};"
        : "+f"(d[0]), "+f"(d[1]), "+f"(d[2]), "+f"(d[3])
        : "r"(a[0]), "r"(a[1]), "r"(a[2]), "r"(a[3]), "r"(b0), "r"(b1));
}
__device__ __forceinline__ void cp16cg(uint32_t dst, const void* src) {
    asm volatile("cp.async.cg.shared.global [%0], [%1], 16;" :: "r"(dst), "l"(src));
}
#define CP_COMMIT() asm volatile("cp.async.commit_group;" ::: "memory")
#define CP_WAIT1()  asm volatile("cp.async.wait_group 1;" ::: "memory")
#define CP_WAIT0()  asm volatile("cp.async.wait_group 0;" ::: "memory")

// ── W fp32 -> fp16 (one-shot) ──
__global__ void wcvt_k(const float* W2, const float* W3, const float* W4,
                       __half* w2h, __half* w3h, __half* w4h) {
    int i = blockIdx.x * 256 + threadIdx.x;   // grid 128 -> 32768 threads
    w2h[i] = __float2half_rn(W2[i]);
    w3h[i] = __float2half_rn(W3[i]);
    if (i < 16384) w4h[i] = __float2half_rn(W4[i]);
}

// ── aggregation (R14): out = act(adj @ z + y); BK=128, 4-way split-K ──
// relu!=0: write hout fp16 ; relu==0: write out fp32.
template <int BN, bool CVT>
__global__ __launch_bounds__(512) void agg_k(
    const float* __restrict__ adjf,
    __half* __restrict__ adjh,
    const __half* __restrict__ zh,
    const float* __restrict__ y,
    float* __restrict__ out,
    __half* __restrict__ hout,
    int relu)
{
    constexpr int NT = 512;
    constexpr int BM = 64, BK = 128, NCH = MROWS / BK;
    constexpr int LDA = 272;
    constexpr int ATILE = BM * LDA;
    constexpr int LDB = BN * 2 + 16;
    constexpr int BTILE = BK * LDB;
    constexpr int BOFF = 2 * ATILE;
    constexpr int CW = BN / 2;
    constexpr int NTN = CW / 8;
    constexpr int NBL = NTN / 2;
    constexpr int NCPB = BK * BN * 2 / 16;
    constexpr int BCP = NCPB / NT;
    constexpr int CPRB = BN / 8;

    extern __shared__ __align__(128) char sm[];
    const uint32_t smb = smem_u32(sm);
    const int tid = threadIdx.x, m0 = blockIdx.x * BM;
    const int w = tid >> 5, lane = tid & 31;
    const int kw = w >> 2, wi = w & 3;
    const int wr = wi >> 1, wc = wi & 1;

    float acc[2][NTN][4];
#pragma unroll
    for (int mt = 0; mt < 2; mt++)
#pragma unroll
        for (int nt = 0; nt < NTN; nt++)
#pragma unroll
            for (int q = 0; q < 4; q++) acc[mt][nt][q] = 0.f;

    float4 raf[4];
    uint4  rah[2];

    auto prefA = [&](int chunk) {
        const size_t kb = (size_t)chunk * BK;
        if (CVT) {
#pragma unroll
            for (int u = 0; u < 4; u++) {
                int id = tid + u * NT, row = id >> 5, c = id & 31;
                raf[u] = *reinterpret_cast<const float4*>(
                    adjf + (size_t)(m0 + row) * MROWS + kb + c * 4);
            }
        } else {
#pragma unroll
            for (int u = 0; u < 2; u++) {
                int id = tid + u * NT, row = id >> 4, c = id & 15;
                rah[u] = *reinterpret_cast<const uint4*>(
                    adjh + (size_t)(m0 + row) * MROWS + kb + c * 8);
            }
        }
    };
    auto commitA = [&](int sa, int chunk) {
        const size_t kb = (size_t)chunk * BK;
        if (CVT) {
#pragma unroll
            for (int u = 0; u < 4; u++) {
                int id = tid + u * NT, row = id >> 5, c = id & 31;
                uint32_t h01 = packh2(raf[u].x * A_SCALE, raf[u].y * A_SCALE);
                uint32_t h23 = packh2(raf[u].z * A_SCALE, raf[u].w * A_SCALE);
                uint32_t off = (uint32_t)(row * LDA + c * 8);
                *reinterpret_cast<uint2*>(sm + sa * ATILE + off) =
                    make_uint2(h01, h23);
                *reinterpret_cast<uint2*>(
                    adjh + (size_t)(m0 + row) * MROWS + kb + c * 4) =
                    make_uint2(h01, h23);
            }
        } else {
#pragma unroll
            for (int u = 0; u < 2; u++) {
                int id = tid + u * NT, row = id >> 4, c = id & 15;
                *reinterpret_cast<uint4*>(sm + sa * ATILE + row * LDA + c * 16) =
                    rah[u];
            }
        }
    };
    auto issueB = [&](int chunk) {
        const uint32_t base = smb + BOFF + (chunk % 3) * BTILE;
        const size_t kb = (size_t)chunk * BK;
#pragma unroll
        for (int u = 0; u < BCP; u++) {
            int id = tid + u * NT;
            int krow = id / CPRB, c = id % CPRB;
            cp16cg(base + (uint32_t)(krow * LDB + c * 16),
                   zh + (kb + krow) * BN + c * 8);
        }
    };

    const uint32_t a_lrow =
        (uint32_t)(wr * 32 + (lane & 15)) * LDA + (lane >> 4) * 16;

    auto compute = [&](int sa, int sb) {
        const uint32_t ab = smb + sa * ATILE;
        const uint32_t bb = smb + BOFF + sb * BTILE;
#pragma unroll
        for (int s = 0; s < 2; s++) {
            const int ks = kw * 2 + s;
            uint32_t ah[2][4];
#pragma unroll
            for (int mt = 0; mt < 2; mt++)
                ldsm_x4(ah[mt], ab + a_lrow + mt * (16 * LDA) + ks * 32);
            uint32_t zb[NBL][4];
#pragma unroll
            for (int bt = 0; bt < NBL; bt++) {
                int krow = ks * 16 + (lane & 15);
                int ncol = wc * CW + bt * 16 + (lane >> 4) * 8;
                ldsm_x4_t(zb[bt], bb + (uint32_t)(krow * LDB + ncol * 2));
            }
#pragma unroll
            for (int mt = 0; mt < 2; mt++)
#pragma unroll
                for (int nt = 0; nt < NTN; nt++) {
                    const int g = nt >> 1, p = (nt & 1) * 2;
                    mma_f16(acc[mt][nt], ah[mt], zb[g][p], zb[g][p + 1]);
                }
        }
    };

    issueB(0); CP_COMMIT();
    issueB(1); CP_COMMIT();
    prefA(0);
    commitA(0, 0);
    prefA(1);

    for (int i = 0; i < NCH; i++) {
        const int sa = i & 1, sb = i % 3;
        CP_WAIT1();
        __syncthreads();
        compute(sa, sb);
        if (i + 2 < NCH) { issueB(i + 2); CP_COMMIT(); }
        if (i + 1 < NCH) {
            commitA((i + 1) & 1, i + 1);
            if (i + 2 < NCH) prefA(i + 2);
        }
    }

    __syncthreads();
    float* ps = reinterpret_cast<float*>(sm);
#pragma unroll 1
    for (int p = 1; p < 4; p++) {
        if (kw == p) {
#pragma unroll
            for (int mt = 0; mt < 2; mt++)
#pragma unroll
                for (int nt = 0; nt < NTN; nt++)
#pragma unroll
                    for (int q = 0; q < 4; q++)
                        ps[((((wi * 2 + mt) * NTN + nt) * 4) + q) * 32 + lane] =
                            acc[mt][nt][q];
        }
        __syncthreads();
        if (kw == 0) {
#pragma unroll
            for (int mt = 0; mt < 2; mt++)
#pragma unroll
                for (int nt = 0; nt < NTN; nt++)
#pragma unroll
                    for (int q = 0; q < 4; q++)
                        acc[mt][nt][q] +=
                            ps[((((wi * 2 + mt) * NTN + nt) * 4) + q) * 32 + lane];
        }
        __syncthreads();
    }
    if (kw == 0) {
        const int g = lane >> 2, cp2 = (lane & 3) * 2;
#pragma unroll
        for (int mt = 0; mt < 2; mt++) {
            const int r0 = m0 + wr * 32 + mt * 16 + g;
#pragma unroll
            for (int nt = 0; nt < NTN; nt++) {
                const int col = wc * CW + nt * 8 + cp2;
#pragma unroll
                for (int half = 0; half < 2; half++) {
                    const size_t row = (size_t)(r0 + half * 8);
                    float2 yv = *reinterpret_cast<const float2*>(y + row * BN + col);
                    float v0 = acc[mt][nt][2 * half + 0] * A_INV + yv.x;
                    float v1 = acc[mt][nt][2 * half + 1] * A_INV + yv.y;
                    if (relu) {
                        v0 = fmaxf(v0, 0.f); v1 = fmaxf(v1, 0.f);
                        *reinterpret_cast<uint32_t*>(hout + row * BN + col) =
                            packh2(v0, v1);
                    } else {
                        *reinterpret_cast<float2*>(out + row * BN + col) =
                            make_float2(v0, v1);
                    }
                }
            }
        }
    }
}

// ── MMA projection (K=128, single-shot): y = hh@Wh[0:K]+b ; z = hh@Wh[K:2K] ──
template <int BN>
__global__ __launch_bounds__(256) void projmma_k(
    const __half* __restrict__ hh,     // [8192, 128] fp16
    const __half* __restrict__ wh,     // [256, BN] fp16 (self ; neigh)
    const float* __restrict__ bias,
    float* __restrict__ yout,
    __half* __restrict__ zh)
{
    constexpr int NT = 256, BM = 64, K = 128;
    constexpr int LDA = 272;
    constexpr int ATILE = BM * LDA;
    constexpr int LDB = BN * 2 + 16;
    constexpr int BTILE = K * LDB;
    constexpr int CW = BN / 4;                 // 32 / 16
    constexpr int NTN = CW / 8;                // 4 / 2
    constexpr int NBL = NTN / 2;               // 2 / 1
    constexpr int CPRB = BN / 8;
    constexpr int WCP = K * BN * 2 / 16 / NT;  // 8 / 4 cp16 per W tile

    extern __shared__ __align__(128) char sm[];
    const uint32_t smb = smem_u32(sm);
    const int tid = threadIdx.x, m0 = blockIdx.x * BM;
    const int w = tid >> 5, lane = tid & 31;
    const int wr = w >> 2, wc = w & 3;         // 2 x 4 warp tiles (32 x CW)

    // loads: A tile + Ws + Wn
#pragma unroll
    for (int u = 0; u < 4; u++) {
        int id = tid + u * NT, row = id >> 4, c = id & 15;
        cp16cg(smb + (uint32_t)(row * LDA + c * 16),
               hh + (size_t)(m0 + row) * K + c * 8);
    }
#pragma unroll
    for (int u = 0; u < WCP; u++) {
        int id = tid + u * NT, row = id / CPRB, c = id % CPRB;
        cp16cg(smb + ATILE + (uint32_t)(row * LDB + c * 16),
               wh + (size_t)row * BN + c * 8);
        cp16cg(smb + ATILE + BTILE + (uint32_t)(row * LDB + c * 16),
               wh + (size_t)(K + row) * BN + c * 8);
    }
    CP_COMMIT();

    float accS[2][NTN][4], accN[2][NTN][4];
#pragma unroll
    for (int mt = 0; mt < 2; mt++)
#pragma unroll
        for (int nt = 0; nt < NTN; nt++)
#pragma unroll
            for (int q = 0; q < 4; q++) { accS[mt][nt][q] = 0.f; accN[mt][nt][q] = 0.f; }

    CP_WAIT0();
    __syncthreads();

    const uint32_t a_lrow =
        (uint32_t)(wr * 32 + (lane & 15)) * LDA + (lane >> 4) * 16;
    const uint32_t bs_base = smb + ATILE;
    const uint32_t bn_base = smb + ATILE + BTILE;

#pragma unroll
    for (int ks = 0; ks < 8; ks++) {
        uint32_t ah[2][4];
#pragma unroll
        for (int mt = 0; mt < 2; mt++)
            ldsm_x4(ah[mt], smb + a_lrow + mt * (16 * LDA) + ks * 32);
        uint32_t wsf[NBL][4], wnf[NBL][4];
#pragma unroll
        for (int bt = 0; bt < NBL; bt++) {
            int krow = ks * 16 + (lane & 15);
            int ncol = wc * CW + bt * 16 + (lane >> 4) * 8;
            uint32_t off = (uint32_t)(krow * LDB + ncol * 2);
            ldsm_x4_t(wsf[bt], bs_base + off);
            ldsm_x4_t(wnf[bt], bn_base + off);
        }
#pragma unroll
        for (int mt = 0; mt < 2; mt++)
#pragma unroll
            for (int nt = 0; nt < NTN; nt++) {
                const int g = nt >> 1, p = (nt & 1) * 2;
                mma_f16(accS[mt][nt], ah[mt], wsf[g][p], wsf[g][p + 1]);
                mma_f16(accN[mt][nt], ah[mt], wnf[g][p], wnf[g][p + 1]);
            }
    }

    // epilogue
    const int g = lane >> 2, cp2 = (lane & 3) * 2;
#pragma unroll
    for (int mt = 0; mt < 2; mt++) {
        const int r0 = m0 + wr * 32 + mt * 16 + g;
#pragma unroll
        for (int nt = 0; nt < NTN; nt++) {
            const int col = wc * CW + nt * 8 + cp2;
            const float b0 = bias[col], b1 = bias[col + 1];
#pragma unroll
            for (int half = 0; half < 2; half++) {
                const size_t row = (size_t)(r0 + half * 8);
                float y0 = accS[mt][nt][2 * half + 0] + b0;
                float y1 = accS[mt][nt][2 * half + 1] + b1;
                *reinterpret_cast<float2*>(yout + row * BN + col) =
                    make_float2(y0, y1);
                *reinterpret_cast<uint32_t*>(zh + row * BN + col) =
                    packh2(accN[mt][nt][2 * half + 0],
                           accN[mt][nt][2 * half + 1]);
            }
        }
    }
}

// ── SIMT fused projection (layer 1, fp32 x, K=256) ──
template <int BN, int NT>
__global__ __launch_bounds__(NT) void proj_k(
    const float* __restrict__ A,
    const float* __restrict__ W,
    const float* __restrict__ bias,
    float* __restrict__ yout,
    __half* __restrict__ zh,
    int K)
{
    constexpr int BM = 64, BK = 16, TM = 4, TN = 8;
    constexpr int AF4 = (BM * BK / 4) / NT;
    constexpr int BF4 = (BK * BN / 4) / NT;
    __shared__ float As[BK][BM];
    __shared__ float Bs[BK][BN];
    __shared__ float Bn[BK][BN];

    const float* Ws = W;
    const float* Wn = W + (size_t)K * BN;
    const int tid = threadIdx.x;
    const int tx = tid % (BN / TN), ty = tid / (BN / TN);
    const int m0 = blockIdx.x * BM;

    float accS[TM][TN], accN[TM][TN];
#pragma unroll
    for (int i = 0; i < TM; i++)
#pragma unroll
        for (int j = 0; j < TN; j++) { accS[i][j] = 0.f; accN[i][j] = 0.f; }

    float4 ra[AF4], rs[BF4], rn[BF4];
    const int nkt = K / BK;

#pragma unroll
    for (int u = 0; u < AF4; u++) {
        int id = tid + u * NT, row = id >> 2, k4 = id & 3;
        ra[u] = *reinterpret_cast<const float4*>(A + (size_t)(m0 + row) * K + k4 * 4);
    }
#pragma unroll
    for (int u = 0; u < BF4; u++) {
        int id = tid + u * NT, row = id / (BN / 4), c4 = id % (BN / 4);
        rs[u] = *reinterpret_cast<const float4*>(Ws + (size_t)row * BN + c4 * 4);
        rn[u] = *reinterpret_cast<const float4*>(Wn + (size_t)row * BN + c4 * 4);
    }
    for (int kt = 0; kt < nkt; ++kt) {
#pragma unroll
        for (int u = 0; u < AF4; u++) {
            int id = tid + u * NT, row = id >> 2, k4 = id & 3;
            As[k4 * 4 + 0][row] = ra[u].x; As[k4 * 4 + 1][row] = ra[u].y;
            As[k4 * 4 + 2][row] = ra[u].z; As[k4 * 4 + 3][row] = ra[u].w;
        }
#pragma unroll
        for (int u = 0; u < BF4; u++) {
            int id = tid + u * NT, row = id / (BN / 4), c4 = id % (BN / 4);
            *reinterpret_cast<float4*>(&Bs[row][c4 * 4]) = rs[u];
            *reinterpret_cast<float4*>(&Bn[row][c4 * 4]) = rn[u];
        }
        __syncthreads();
        if (kt + 1 < nkt) {
            const int kb = (kt + 1) * BK;
#pragma unroll
            for (int u = 0; u < AF4; u++) {
                int id = tid + u * NT, row = id >> 2, k4 = id & 3;
                ra[u] = *reinterpret_cast<const float4*>(
                    A + (size_t)(m0 + row) * K + kb + k4 * 4);
            }
#pragma unroll
            for (int u = 0; u < BF4; u++) {
                int id = tid + u * NT, row = id / (BN / 4), c4 = id % (BN / 4);
                rs[u] = *reinterpret_cast<const float4*>(
                    Ws + (size_t)(kb + row) * BN + c4 * 4);
                rn[u] = *reinterpret_cast<const float4*>(
                    Wn + (size_t)(kb + row) * BN + c4 * 4);
            }
        }
#pragma unroll
        for (int k = 0; k < BK; k++) {
            float a[TM], bs[TN], bn[TN];
            *reinterpret_cast<float4*>(a) =
                *reinterpret_cast<const float4*>(&As[k][ty * TM]);
            *reinterpret_cast<float4*>(bs) =
                *reinterpret_cast<const float4*>(&Bs[k][tx * TN]);
            *reinterpret_cast<float4*>(bs + 4) =
                *reinterpret_cast<const float4*>(&Bs[k][tx * TN + 4]);
            *reinterpret_cast<float4*>(bn) =
                *reinterpret_cast<const float4*>(&Bn[k][tx * TN]);
            *reinterpret_cast<float4*>(bn + 4) =
                *reinterpret_cast<const float4*>(&Bn[k][tx * TN + 4]);
#pragma unroll
            for (int i = 0; i < TM; i++)
#pragma unroll
                for (int j = 0; j < TN; j++) {
                    accS[i][j] = fmaf(a[i], bs[j], accS[i][j]);
                    accN[i][j] = fmaf(a[i], bn[j], accN[i][j]);
                }
        }
        __syncthreads();
    }
#pragma unroll
    for (int i = 0; i < TM; i++) {
        const int row = m0 + ty * TM + i;
#pragma unroll
        for (int j = 0; j < TN; j += 4) {
            const int col = tx * TN + j;
            float4 v = make_float4(accS[i][j], accS[i][j+1], accS[i][j+2], accS[i][j+3]);
            float4 c = *reinterpret_cast<const float4*>(bias + col);
            v.x += c.x; v.y += c.y; v.z += c.z; v.w += c.w;
            *reinterpret_cast<float4*>(yout + (size_t)row * BN + col) = v;
        }
#pragma unroll
        for (int j = 0; j < TN; j += 2) {
            const int col = tx * TN + j;
            *reinterpret_cast<uint32_t*>(zh + (size_t)row * BN + col) =
                packh2(accN[i][j], accN[i][j + 1]);
        }
    }
}

extern "C" void kernel_launch(void* const* d_in, const int* in_sizes, int n_in,
                              void* d_out, int out_size)
{
    const float* x   = (const float*)d_in[0];
    const float* adj = (const float*)d_in[1];
    const float* W1  = (const float*)d_in[2];
    const float* b1  = (const float*)d_in[3];
    const float* W2  = (const float*)d_in[4];
    const float* b2  = (const float*)d_in[5];
    const float* W3  = (const float*)d_in[6];
    const float* b3  = (const float*)d_in[7];
    const float* W4  = (const float*)d_in[8];
    const float* b4  = (const float*)d_in[9];
    float* out = (float*)d_out;

    float* y;
    __half *zh, *hh, *adjh, *w2h, *w3h, *w4h;
    cudaGetSymbolAddress((void**)&y,    g_y);
    cudaGetSymbolAddress((void**)&zh,   g_zh);
    cudaGetSymbolAddress((void**)&hh,   g_hh);
    cudaGetSymbolAddress((void**)&adjh, g_adjh);
    cudaGetSymbolAddress((void**)&w2h,  g_w2h);
    cudaGetSymbolAddress((void**)&w3h,  g_w3h);
    cudaGetSymbolAddress((void**)&w4h,  g_w4h);

    constexpr int SM128 = 2 * (64 * 272) + 3 * (128 * (128 * 2 + 16)); // 139264
    constexpr int SM64  = 2 * (64 * 272) + 3 * (128 * (64 * 2 + 16));  //  90112
    constexpr int SP128 = 64 * 272 + 2 * (128 * (128 * 2 + 16));       //  87040
    constexpr int SP64  = 64 * 272 + 2 * (128 * (64 * 2 + 16));        //  54272
    cudaFuncSetAttribute(agg_k<128, true>,  cudaFuncAttributeMaxDynamicSharedMemorySize, SM128);
    cudaFuncSetAttribute(agg_k<128, false>, cudaFuncAttributeMaxDynamicSharedMemorySize, SM128);
    cudaFuncSetAttribute(agg_k<64,  false>, cudaFuncAttributeMaxDynamicSharedMemorySize, SM64);
    cudaFuncSetAttribute(projmma_k<128>, cudaFuncAttributeMaxDynamicSharedMemorySize, SP128);
    cudaFuncSetAttribute(projmma_k<64>,  cudaFuncAttributeMaxDynamicSharedMemorySize, SP64);

    const dim3 pg(MROWS / 64);
    const dim3 ag(MROWS / 64);

    wcvt_k<<<128, 256>>>(W2, W3, W4, w2h, w3h, w4h);

    proj_k<128, 256><<<pg, 256>>>(x, W1, b1, y, zh, 256);
    agg_k<128, true ><<<ag, 512, SM128>>>(adj, adjh, zh, y, nullptr, hh, 1);

    projmma_k<128><<<pg, 256, SP128>>>(hh, w2h, b2, y, zh);
    agg_k<128, false><<<ag, 512, SM128>>>(nullptr, adjh, zh, y, nullptr, hh, 1);

    projmma_k<128><<<pg, 256, SP128>>>(hh, w3h, b3, y, zh);
    agg_k<128, false><<<ag, 512, SM128>>>(nullptr, adjh, zh, y, nullptr, hh, 1);

    projmma_k<64><<<pg, 256, SP64>>>(hh, w4h, b4, y, zh);
    agg_k<64,  false><<<ag, 512, SM64>>>(nullptr, adjh, zh, y, out, nullptr, 0);
}

// round 16
// speedup vs baseline: 1.7021x; 1.0622x over previous
#include <cuda_runtime.h>
#include <cuda_fp16.h>
#include <stdint.h>

// GraphSAGE 4-layer, dense adj. N=8192, F: 256->128->128->64.
// h = act( h@W_self + adj @ (h@W_neigh) + b ).
// R16: next-layer projection fused into the agg epilogue (h stays in smem,
// W fp16 staged at kernel start, 8 warps run the projmma fragment code).
// Layer-1 projection = single-shot MMA on fp16 x. z ping-pongs (zhA/zhB).
// Mainloop identical to R14/R15 (BK=128, 4-way split-K, cp.async.cg B ring).

static constexpr int MROWS = 8192;
static constexpr float A_SCALE = 4096.0f;
static constexpr float A_INV   = 1.0f / 4096.0f;

__device__ float g_y [8192 * 128];
__device__ __align__(16) __half g_zha[8192 * 128];
__device__ __align__(16) __half g_zhb[8192 * 128];
__device__ __align__(16) __half g_xh [8192 * 256];
__device__ __align__(16) __half g_adjh[(size_t)8192 * 8192];
__device__ __align__(16) __half g_w1h[512 * 128];
__device__ __align__(16) __half g_w2h[256 * 128];
__device__ __align__(16) __half g_w3h[256 * 128];
__device__ __align__(16) __half g_w4h[256 * 64];

__device__ __forceinline__ uint32_t smem_u32(const void* p) {
    uint32_t a;
    asm("{ .reg .u64 t; cvta.to.shared.u64 t, %1; cvt.u32.u64 %0, t; }"
        : "=r"(a) : "l"(p));
    return a;
}
__device__ __forceinline__ uint32_t packh2(float a, float b) {
    __half2 t = __floats2half2_rn(a, b);
    return *reinterpret_cast<uint32_t*>(&t);
}
__device__ __forceinline__ void ldsm_x4(uint32_t* r, uint32_t addr) {
    asm volatile("ldmatrix.sync.aligned.m8n8.x4.shared.b16 {%0,%1,%2,%3}, [%4];"
                 : "=r"(r[0]), "=r"(r[1]), "=r"(r[2]), "=r"(r[3]) : "r"(addr));
}
__device__ __forceinline__ void ldsm_x4_t(uint32_t* r, uint32_t addr) {
    asm volatile("ldmatrix.sync.aligned.m8n8.x4.trans.shared.b16 {%0,%1,%2,%3}, [%4];"
                 : "=r"(r[0]), "=r"(r[1]), "=r"(r[2]), "=r"(r[3]) : "r"(addr));
}
__device__ __forceinline__ void mma_f16(float* d, const uint32_t* a,
                                        uint32_t b0, uint32_t b1) {
    asm volatile(
        "mma.sync.aligned.m16n8k16.row.col.f32.f16.f16.f32 "
        "{%0,%1,%2,%3}, {%4,%5,%6,%7}, {%8,%9}, {%0,%1,%2,%3};"
        : "+f"(d[0]), "+f"(d[1]), "+f"(d[2]), "+f"(d[3])
        : "r"(a[0]), "r"(a[1]), "r"(a[2]), "r"(a[3]), "r"(b0), "r"(b1));
}
__device__ __forceinline__ void cp16cg(uint32_t dst, const void* src) {
    asm volatile("cp.async.cg.shared.global [%0], [%1], 16;" :: "r"(dst), "l"(src));
}
#define CP_COMMIT() asm volatile("cp.async.commit_group;" ::: "memory")
#define CP_WAIT1()  asm volatile("cp.async.wait_group 1;" ::: "memory")
#define CP_WAIT0()  asm volatile("cp.async.wait_group 0;" ::: "memory")

// ── one-shot converts: x and all W to fp16 ──
__global__ void cvt_k(const float* x, const float* W1, const float* W2,
                      const float* W3, const float* W4,
                      __half* xh, __half* w1h, __half* w2h,
                      __half* w3h, __half* w4h) {
    int i = blockIdx.x * 256 + threadIdx.x;   // grid 8192 -> 2,097,152
    xh[i] = __float2half_rn(x[i]);
    if (i < 65536) w1h[i] = __float2half_rn(W1[i]);
    if (i < 32768) w2h[i] = __float2half_rn(W2[i]);
    if (i < 32768) w3h[i] = __float2half_rn(W3[i]);
    if (i < 16384) w4h[i] = __float2half_rn(W4[i]);
}

// ── single-shot MMA projection (layer 1): y = A@Wh[0:K]+b ; z = A@Wh[K:2K] ──
template <int K, int BN>
__global__ __launch_bounds__(256) void projmma_k(
    const __half* __restrict__ ah,     // [8192, K] fp16
    const __half* __restrict__ wh,     // [2K, BN] fp16
    const float* __restrict__ bias,
    float* __restrict__ yout,
    __half* __restrict__ zh)
{
    constexpr int NT = 256, BM = 64;
    constexpr int LDA = K * 2 + 16;
    constexpr int ATILE = BM * LDA;
    constexpr int LDB = BN * 2 + 16;
    constexpr int BTILE = K * LDB;
    constexpr int CW = BN / 4, NTN = CW / 8, NBL = NTN / 2;
    constexpr int ACP = (BM * K * 2 / 16) / NT;   // 8 for K=256
    constexpr int WCP = (K * BN * 2 / 16) / NT;   // 16
    constexpr int APR = K / 8, CPRB = BN / 8;

    extern __shared__ __align__(128) char sm[];
    const uint32_t smb = smem_u32(sm);
    const int tid = threadIdx.x, m0 = blockIdx.x * BM;
    const int w = tid >> 5, lane = tid & 31;
    const int wr = w >> 2, wc = w & 3;

#pragma unroll
    for (int u = 0; u < ACP; u++) {
        int id = tid + u * NT, row = id / APR, c = id % APR;
        cp16cg(smb + (uint32_t)(row * LDA + c * 16),
               ah + (size_t)(m0 + row) * K + c * 8);
    }
#pragma unroll
    for (int u = 0; u < WCP; u++) {
        int id = tid + u * NT, row = id / CPRB, c = id % CPRB;
        cp16cg(smb + ATILE + (uint32_t)(row * LDB + c * 16),
               wh + (size_t)row * BN + c * 8);
        cp16cg(smb + ATILE + BTILE + (uint32_t)(row * LDB + c * 16),
               wh + (size_t)(K + row) * BN + c * 8);
    }
    CP_COMMIT();

    float accS[2][NTN][4], accN[2][NTN][4];
#pragma unroll
    for (int mt = 0; mt < 2; mt++)
#pragma unroll
        for (int nt = 0; nt < NTN; nt++)
#pragma unroll
            for (int q = 0; q < 4; q++) { accS[mt][nt][q] = 0.f; accN[mt][nt][q] = 0.f; }

    CP_WAIT0();
    __syncthreads();

    const uint32_t a_lrow =
        (uint32_t)(wr * 32 + (lane & 15)) * LDA + (lane >> 4) * 16;

#pragma unroll
    for (int ks = 0; ks < K / 16; ks++) {
        uint32_t ahf[2][4];
#pragma unroll
        for (int mt = 0; mt < 2; mt++)
            ldsm_x4(ahf[mt], smb + a_lrow + mt * (16 * LDA) + ks * 32);
        uint32_t wsf[NBL][4], wnf[NBL][4];
#pragma unroll
        for (int bt = 0; bt < NBL; bt++) {
            int krow = ks * 16 + (lane & 15);
            int ncol = wc * CW + bt * 16 + (lane >> 4) * 8;
            uint32_t off = (uint32_t)(krow * LDB + ncol * 2);
            ldsm_x4_t(wsf[bt], smb + ATILE + off);
            ldsm_x4_t(wnf[bt], smb + ATILE + BTILE + off);
        }
#pragma unroll
        for (int mt = 0; mt < 2; mt++)
#pragma unroll
            for (int nt = 0; nt < NTN; nt++) {
                const int g = nt >> 1, p = (nt & 1) * 2;
                mma_f16(accS[mt][nt], ahf[mt], wsf[g][p], wsf[g][p + 1]);
                mma_f16(accN[mt][nt], ahf[mt], wnf[g][p], wnf[g][p + 1]);
            }
    }

    const int g = lane >> 2, cp2 = (lane & 3) * 2;
#pragma unroll
    for (int mt = 0; mt < 2; mt++) {
        const int r0 = m0 + wr * 32 + mt * 16 + g;
#pragma unroll
        for (int nt = 0; nt < NTN; nt++) {
            const int col = wc * CW + nt * 8 + cp2;
            const float b0 = bias[col], b1 = bias[col + 1];
#pragma unroll
            for (int half = 0; half < 2; half++) {
                const size_t row = (size_t)(r0 + half * 8);
                *reinterpret_cast<float2*>(yout + row * BN + col) =
                    make_float2(accS[mt][nt][2 * half] + b0,
                                accS[mt][nt][2 * half + 1] + b1);
                *reinterpret_cast<uint32_t*>(zh + row * BN + col) =
                    packh2(accN[mt][nt][2 * half], accN[mt][nt][2 * half + 1]);
            }
        }
    }
}

// ── aggregation + fused next-layer projection ──
// h = relu(adj@z + y) (BNP>0) kept in smem; then y/z(n+1) = h@W(n+1) (+bias).
// BNP==0: final layer, write out fp32 (no relu).
template <int BN, bool CVT, int BNP>
__global__ __launch_bounds__(512) void agg_k(
    const float* __restrict__ adjf,
    __half* __restrict__ adjh,
    const __half* __restrict__ zh,
    float* __restrict__ y,              // read own rows; BNP: rewritten
    const __half* __restrict__ wh,      // [256, BNP] fp16 (BNP>0)
    const float* __restrict__ bias,     // b(n+1)
    float* __restrict__ out,            // BNP==0
    __half* __restrict__ zout)          // BNP>0
{
    constexpr int NT = 512;
    constexpr int BM = 64, BK = 128, NCH = MROWS / BK;
    constexpr int LDA = 272;
    constexpr int ATILE = BM * LDA;
    constexpr int LDB = BN * 2 + 16;
    constexpr int BTILE = BK * LDB;
    constexpr int BOFF = 2 * ATILE;
    constexpr int CW = BN / 2, NTN = CW / 8, NBL = NTN / 2;
    constexpr int NCPB = BK * BN * 2 / 16, BCP = NCPB / NT, CPRB = BN / 8;
    // fused proj constants
    constexpr int LDBP = (BNP > 0 ? BNP : 8) * 2 + 16;
    constexpr int WTILE = 128 * LDBP;
    constexpr int WOFF = BOFF + 3 * BTILE;
    constexpr int CWP = (BNP > 0 ? BNP : 8) / 4;
    constexpr int NTP = CWP / 8 > 0 ? CWP / 8 : 1;
    constexpr int NBP = NTP / 2 > 0 ? NTP / 2 : 1;

    extern __shared__ __align__(128) char sm[];
    const uint32_t smb = smem_u32(sm);
    const int tid = threadIdx.x, m0 = blockIdx.x * BM;
    const int w = tid >> 5, lane = tid & 31;
    const int kw = w >> 2, wi = w & 3;
    const int wr = wi >> 1, wc = wi & 1;

    // stage W(n+1) (one extra cp.async group; drains with B0)
    if (BNP > 0) {
        constexpr int WCP2 = (BNP > 0 ? (128 * BNP * 2 / 16) / NT : 1);
        constexpr int CPRP = (BNP > 0 ? BNP : 8) / 8;
#pragma unroll
        for (int u = 0; u < WCP2; u++) {
            int id = tid + u * NT, row = id / CPRP, c = id % CPRP;
            cp16cg(smb + WOFF + (uint32_t)(row * LDBP + c * 16),
                   wh + (size_t)row * BNP + c * 8);
            cp16cg(smb + WOFF + WTILE + (uint32_t)(row * LDBP + c * 16),
                   wh + (size_t)(128 + row) * BNP + c * 8);
        }
    }

    float acc[2][NTN][4];
#pragma unroll
    for (int mt = 0; mt < 2; mt++)
#pragma unroll
        for (int nt = 0; nt < NTN; nt++)
#pragma unroll
            for (int q = 0; q < 4; q++) acc[mt][nt][q] = 0.f;

    float4 raf[4];
    uint4  rah[2];

    auto prefA = [&](int chunk) {
        const size_t kb = (size_t)chunk * BK;
        if (CVT) {
#pragma unroll
            for (int u = 0; u < 4; u++) {
                int id = tid + u * NT, row = id >> 5, c = id & 31;
                raf[u] = *reinterpret_cast<const float4*>(
                    adjf + (size_t)(m0 + row) * MROWS + kb + c * 4);
            }
        } else {
#pragma unroll
            for (int u = 0; u < 2; u++) {
                int id = tid + u * NT, row = id >> 4, c = id & 15;
                rah[u] = *reinterpret_cast<const uint4*>(
                    adjh + (size_t)(m0 + row) * MROWS + kb + c * 8);
            }
        }
    };
    auto commitA = [&](int sa, int chunk) {
        const size_t kb = (size_t)chunk * BK;
        if (CVT) {
#pragma unroll
            for (int u = 0; u < 4; u++) {
                int id = tid + u * NT, row = id >> 5, c = id & 31;
                uint32_t h01 = packh2(raf[u].x * A_SCALE, raf[u].y * A_SCALE);
                uint32_t h23 = packh2(raf[u].z * A_SCALE, raf[u].w * A_SCALE);
                uint32_t off = (uint32_t)(row * LDA + c * 8);
                *reinterpret_cast<uint2*>(sm + sa * ATILE + off) =
                    make_uint2(h01, h23);
                *reinterpret_cast<uint2*>(
                    adjh + (size_t)(m0 + row) * MROWS + kb + c * 4) =
                    make_uint2(h01, h23);
            }
        } else {
#pragma unroll
            for (int u = 0; u < 2; u++) {
                int id = tid + u * NT, row = id >> 4, c = id & 15;
                *reinterpret_cast<uint4*>(sm + sa * ATILE + row * LDA + c * 16) =
                    rah[u];
            }
        }
    };
    auto issueB = [&](int chunk) {
        const uint32_t base = smb + BOFF + (chunk % 3) * BTILE;
        const size_t kb = (size_t)chunk * BK;
#pragma unroll
        for (int u = 0; u < BCP; u++) {
            int id = tid + u * NT;
            int krow = id / CPRB, c = id % CPRB;
            cp16cg(base + (uint32_t)(krow * LDB + c * 16),
                   zh + (kb + krow) * BN + c * 8);
        }
    };

    const uint32_t a_lrow =
        (uint32_t)(wr * 32 + (lane & 15)) * LDA + (lane >> 4) * 16;

    auto compute = [&](int sa, int sb) {
        const uint32_t ab = smb + sa * ATILE;
        const uint32_t bb = smb + BOFF + sb * BTILE;
#pragma unroll
        for (int s = 0; s < 2; s++) {
            const int ks = kw * 2 + s;
            uint32_t ahf[2][4];
#pragma unroll
            for (int mt = 0; mt < 2; mt++)
                ldsm_x4(ahf[mt], ab + a_lrow + mt * (16 * LDA) + ks * 32);
            uint32_t zb[NBL][4];
#pragma unroll
            for (int bt = 0; bt < NBL; bt++) {
                int krow = ks * 16 + (lane & 15);
                int ncol = wc * CW + bt * 16 + (lane >> 4) * 8;
                ldsm_x4_t(zb[bt], bb + (uint32_t)(krow * LDB + ncol * 2));
            }
#pragma unroll
            for (int mt = 0; mt < 2; mt++)
#pragma unroll
                for (int nt = 0; nt < NTN; nt++) {
                    const int g = nt >> 1, p = (nt & 1) * 2;
                    mma_f16(acc[mt][nt], ahf[mt], zb[g][p], zb[g][p + 1]);
                }
        }
    };

    issueB(0); CP_COMMIT();           // W (if any) + B0
    issueB(1); CP_COMMIT();
    prefA(0);
    commitA(0, 0);
    prefA(1);

    for (int i = 0; i < NCH; i++) {
        const int sa = i & 1, sb = i % 3;
        CP_WAIT1();
        __syncthreads();
        compute(sa, sb);
        if (i + 2 < NCH) { issueB(i + 2); CP_COMMIT(); }
        if (i + 1 < NCH) {
            commitA((i + 1) & 1, i + 1);
            if (i + 2 < NCH) prefA(i + 2);
        }
    }

    // merge: single publish round (kw 1..3 -> disjoint smem), then kw==0 sums
    __syncthreads();
    float* ps = reinterpret_cast<float*>(sm);
    constexpr int PBASE = ATILE / 4;                // floats
    constexpr int PSZ = 1024 * NTN;                 // floats per kw group
    if (kw > 0) {
#pragma unroll
        for (int mt = 0; mt < 2; mt++)
#pragma unroll
            for (int nt = 0; nt < NTN; nt++)
#pragma unroll
                for (int q = 0; q < 4; q++)
                    ps[PBASE + (kw - 1) * PSZ +
                       ((((wi * 2 + mt) * NTN + nt) * 4) + q) * 32 + lane] =
                        acc[mt][nt][q];
    }
    __syncthreads();
    if (kw == 0) {
        const int g = lane >> 2, cp2 = (lane & 3) * 2;
#pragma unroll
        for (int mt = 0; mt < 2; mt++) {
            const int r0 = m0 + wr * 32 + mt * 16 + g;
#pragma unroll
            for (int nt = 0; nt < NTN; nt++) {
                const int col = wc * CW + nt * 8 + cp2;
                float p[4];
#pragma unroll
                for (int q = 0; q < 4; q++) {
                    int idx = ((((wi * 2 + mt) * NTN + nt) * 4) + q) * 32 + lane;
                    p[q] = acc[mt][nt][q] + ps[PBASE + idx] +
                           ps[PBASE + PSZ + idx] + ps[PBASE + 2 * PSZ + idx];
                }
#pragma unroll
                for (int half = 0; half < 2; half++) {
                    const size_t row = (size_t)(r0 + half * 8);
                    float2 yv = *reinterpret_cast<const float2*>(y + row * BN + col);
                    float v0 = p[2 * half + 0] * A_INV + yv.x;
                    float v1 = p[2 * half + 1] * A_INV + yv.y;
                    if (BNP > 0) {
                        v0 = fmaxf(v0, 0.f); v1 = fmaxf(v1, 0.f);
                        *reinterpret_cast<uint32_t*>(
                            sm + (uint32_t)((r0 + half * 8 - m0) * LDA + col * 2)) =
                            packh2(v0, v1);
                    } else {
                        *reinterpret_cast<float2*>(out + row * BN + col) =
                            make_float2(v0, v1);
                    }
                }
            }
        }
    }

    // fused projection (8 warps), verbatim projmma fragment code
    if (BNP > 0) {
        __syncthreads();
        if (w < 8) {
            const int pwr = w >> 2, pwc = w & 3;
            float accS[2][NTP][4], accN[2][NTP][4];
#pragma unroll
            for (int mt = 0; mt < 2; mt++)
#pragma unroll
                for (int nt = 0; nt < NTP; nt++)
#pragma unroll
                    for (int q = 0; q < 4; q++) { accS[mt][nt][q] = 0.f; accN[mt][nt][q] = 0.f; }

            const uint32_t pa_lrow =
                (uint32_t)(pwr * 32 + (lane & 15)) * LDA + (lane >> 4) * 16;
#pragma unroll
            for (int ks = 0; ks < 8; ks++) {
                uint32_t ahf[2][4];
#pragma unroll
                for (int mt = 0; mt < 2; mt++)
                    ldsm_x4(ahf[mt], smb + pa_lrow + mt * (16 * LDA) + ks * 32);
                uint32_t wsf[NBP][4], wnf[NBP][4];
#pragma unroll
                for (int bt = 0; bt < NBP; bt++) {
                    int krow = ks * 16 + (lane & 15);
                    int ncol = pwc * CWP + bt * 16 + (lane >> 4) * 8;
                    uint32_t off = (uint32_t)(krow * LDBP + ncol * 2);
                    ldsm_x4_t(wsf[bt], smb + WOFF + off);
                    ldsm_x4_t(wnf[bt], smb + WOFF + WTILE + off);
                }
#pragma unroll
                for (int mt = 0; mt < 2; mt++)
#pragma unroll
                    for (int nt = 0; nt < NTP; nt++) {
                        const int g = nt >> 1, p = (nt & 1) * 2;
                        mma_f16(accS[mt][nt], ahf[mt], wsf[g][p], wsf[g][p + 1]);
                        mma_f16(accN[mt][nt], ahf[mt], wnf[g][p], wnf[g][p + 1]);
                    }
            }
            const int g = lane >> 2, cp2 = (lane & 3) * 2;
#pragma unroll
            for (int mt = 0; mt < 2; mt++) {
                const int r0 = m0 + pwr * 32 + mt * 16 + g;
#pragma unroll
                for (int nt = 0; nt < NTP; nt++) {
                    const int col = pwc * CWP + nt * 8 + cp2;
                    const float b0 = bias[col], b1 = bias[col + 1];
#pragma unroll
                    for (int half = 0; half < 2; half++) {
                        const size_t row = (size_t)(r0 + half * 8);
                        *reinterpret_cast<float2*>(y + row * BNP + col) =
                            make_float2(accS[mt][nt][2 * half] + b0,
                                        accS[mt][nt][2 * half + 1] + b1);
                        *reinterpret_cast<uint32_t*>(zout + row * BNP + col) =
                            packh2(accN[mt][nt][2 * half],
                                   accN[mt][nt][2 * half + 1]);
                    }
                }
            }
        }
    }
}

extern "C" void kernel_launch(void* const* d_in, const int* in_sizes, int n_in,
                              void* d_out, int out_size)
{
    const float* x   = (const float*)d_in[0];
    const float* adj = (const float*)d_in[1];
    const float* W1  = (const float*)d_in[2];
    const float* b1  = (const float*)d_in[3];
    const float* W2  = (const float*)d_in[4];
    const float* b2  = (const float*)d_in[5];
    const float* W3  = (const float*)d_in[6];
    const float* b3  = (const float*)d_in[7];
    const float* W4  = (const float*)d_in[8];
    const float* b4  = (const float*)d_in[9];
    float* out = (float*)d_out;

    float* y;
    __half *zha, *zhb, *xh, *adjh, *w1h, *w2h, *w3h, *w4h;
    cudaGetSymbolAddress((void**)&y,    g_y);
    cudaGetSymbolAddress((void**)&zha,  g_zha);
    cudaGetSymbolAddress((void**)&zhb,  g_zhb);
    cudaGetSymbolAddress((void**)&xh,   g_xh);
    cudaGetSymbolAddress((void**)&adjh, g_adjh);
    cudaGetSymbolAddress((void**)&w1h,  g_w1h);
    cudaGetSymbolAddress((void**)&w2h,  g_w2h);
    cudaGetSymbolAddress((void**)&w3h,  g_w3h);
    cudaGetSymbolAddress((void**)&w4h,  g_w4h);

    // agg smem: base (A2 + B3) + W tiles for fused proj
    constexpr int BASE128 = 2 * (64 * 272) + 3 * (128 * (128 * 2 + 16)); // 139264
    constexpr int BASE64  = 2 * (64 * 272) + 3 * (128 * (64 * 2 + 16));  //  90112
    constexpr int SMA_P128 = BASE128 + 2 * (128 * (128 * 2 + 16));       // 208896
    constexpr int SMA_P64  = BASE128 + 2 * (128 * (64 * 2 + 16));        // 176128
    constexpr int SP1 = 64 * (256 * 2 + 16) + 2 * (256 * (128 * 2 + 16)); // 173056
    cudaFuncSetAttribute(agg_k<128, true, 128>,  cudaFuncAttributeMaxDynamicSharedMemorySize, SMA_P128);
    cudaFuncSetAttribute(agg_k<128, false, 128>, cudaFuncAttributeMaxDynamicSharedMemorySize, SMA_P128);
    cudaFuncSetAttribute(agg_k<128, false, 64>,  cudaFuncAttributeMaxDynamicSharedMemorySize, SMA_P64);
    cudaFuncSetAttribute(agg_k<64,  false, 0>,   cudaFuncAttributeMaxDynamicSharedMemorySize, BASE64);
    cudaFuncSetAttribute(projmma_k<256, 128>, cudaFuncAttributeMaxDynamicSharedMemorySize, SP1);

    const dim3 ag(MROWS / 64);

    cvt_k<<<8192, 256>>>(x, W1, W2, W3, W4, xh, w1h, w2h, w3h, w4h);

    // layer 1 projection (MMA, K=256)
    projmma_k<256, 128><<<ag, 256, SP1>>>(xh, w1h, b1, y, zha);
    // layer 1 agg + fused proj2
    agg_k<128, true, 128><<<ag, 512, SMA_P128>>>(adj, adjh, zha, y, w2h, b2, nullptr, zhb);
    // layer 2 agg + fused proj3
    agg_k<128, false, 128><<<ag, 512, SMA_P128>>>(nullptr, adjh, zhb, y, w3h, b3, nullptr, zha);
    // layer 3 agg + fused proj4
    agg_k<128, false, 64><<<ag, 512, SMA_P64>>>(nullptr, adjh, zha, y, w4h, b4, nullptr, zhb);
    // layer 4 agg -> out
    agg_k<64, false, 0><<<ag, 512, BASE64>>>(nullptr, adjh, zhb, y, nullptr, nullptr, out, nullptr);
}

// round 17
// speedup vs baseline: 1.7154x; 1.0078x over previous
#include <cuda_runtime.h>
#include <cuda_fp16.h>
#include <stdint.h>

// GraphSAGE 4-layer, dense adj. N=8192, F: 256->128->128->64.
// R17: R16 structure; final agg (BN=64) moves to BK=256 (half the barriers,
// 3-stage B ring fits); issueB hoisted before compute in all aggs.
// Steady-state BN=128 aggs are at the fallback-HMMA issue floor (rt~16).

static constexpr int MROWS = 8192;
static constexpr float A_SCALE = 4096.0f;
static constexpr float A_INV   = 1.0f / 4096.0f;

__device__ float g_y [8192 * 128];
__device__ __align__(16) __half g_zha[8192 * 128];
__device__ __align__(16) __half g_zhb[8192 * 128];
__device__ __align__(16) __half g_xh [8192 * 256];
__device__ __align__(16) __half g_adjh[(size_t)8192 * 8192];
__device__ __align__(16) __half g_w1h[512 * 128];
__device__ __align__(16) __half g_w2h[256 * 128];
__device__ __align__(16) __half g_w3h[256 * 128];
__device__ __align__(16) __half g_w4h[256 * 64];

__device__ __forceinline__ uint32_t smem_u32(const void* p) {
    uint32_t a;
    asm("{ .reg .u64 t; cvta.to.shared.u64 t, %1; cvt.u32.u64 %0, t; }"
        : "=r"(a) : "l"(p));
    return a;
}
__device__ __forceinline__ uint32_t packh2(float a, float b) {
    __half2 t = __floats2half2_rn(a, b);
    return *reinterpret_cast<uint32_t*>(&t);
}
__device__ __forceinline__ void ldsm_x4(uint32_t* r, uint32_t addr) {
    asm volatile("ldmatrix.sync.aligned.m8n8.x4.shared.b16 {%0,%1,%2,%3}, [%4];"
                 : "=r"(r[0]), "=r"(r[1]), "=r"(r[2]), "=r"(r[3]) : "r"(addr));
}
__device__ __forceinline__ void ldsm_x4_t(uint32_t* r, uint32_t addr) {
    asm volatile("ldmatrix.sync.aligned.m8n8.x4.trans.shared.b16 {%0,%1,%2,%3}, [%4];"
                 : "=r"(r[0]), "=r"(r[1]), "=r"(r[2]), "=r"(r[3]) : "r"(addr));
}
__device__ __forceinline__ void mma_f16(float* d, const uint32_t* a,
                                        uint32_t b0, uint32_t b1) {
    asm volatile(
        "mma.sync.aligned.m16n8k16.row.col.f32.f16.f16.f32 "
        "{%0,%1,%2,%3}, {%4,%5,%6,%7}, {%8,%9}, {%0,%1,%2,%3};"
        : "+f"(d[0]), "+f"(d[1]), "+f"(d[2]), "+f"(d[3])
        : "r"(a[0]), "r"(a[1]), "r"(a[2]), "r"(a[3]), "r"(b0), "r"(b1));
}
__device__ __forceinline__ void cp16cg(uint32_t dst, const void* src) {
    asm volatile("cp.async.cg.shared.global [%0], [%1], 16;" :: "r"(dst), "l"(src));
}
#define CP_COMMIT() asm volatile("cp.async.commit_group;" ::: "memory")
#define CP_WAIT1()  asm volatile("cp.async.wait_group 1;" ::: "memory")
#define CP_WAIT0()  asm volatile("cp.async.wait_group 0;" ::: "memory")

// ── one-shot converts ──
__global__ void cvt_k(const float* x, const float* W1, const float* W2,
                      const float* W3, const float* W4,
                      __half* xh, __half* w1h, __half* w2h,
                      __half* w3h, __half* w4h) {
    int i = blockIdx.x * 256 + threadIdx.x;
    xh[i] = __float2half_rn(x[i]);
    if (i < 65536) w1h[i] = __float2half_rn(W1[i]);
    if (i < 32768) w2h[i] = __float2half_rn(W2[i]);
    if (i < 32768) w3h[i] = __float2half_rn(W3[i]);
    if (i < 16384) w4h[i] = __float2half_rn(W4[i]);
}

// ── single-shot MMA projection (layer 1) ──
template <int K, int BN>
__global__ __launch_bounds__(256) void projmma_k(
    const __half* __restrict__ ah,
    const __half* __restrict__ wh,
    const float* __restrict__ bias,
    float* __restrict__ yout,
    __half* __restrict__ zh)
{
    constexpr int NT = 256, BM = 64;
    constexpr int LDA = K * 2 + 16;
    constexpr int ATILE = BM * LDA;
    constexpr int LDB = BN * 2 + 16;
    constexpr int BTILE = K * LDB;
    constexpr int CW = BN / 4, NTN = CW / 8, NBL = NTN / 2;
    constexpr int ACP = (BM * K * 2 / 16) / NT;
    constexpr int WCP = (K * BN * 2 / 16) / NT;
    constexpr int APR = K / 8, CPRB = BN / 8;

    extern __shared__ __align__(128) char sm[];
    const uint32_t smb = smem_u32(sm);
    const int tid = threadIdx.x, m0 = blockIdx.x * BM;
    const int w = tid >> 5, lane = tid & 31;
    const int wr = w >> 2, wc = w & 3;

#pragma unroll
    for (int u = 0; u < ACP; u++) {
        int id = tid + u * NT, row = id / APR, c = id % APR;
        cp16cg(smb + (uint32_t)(row * LDA + c * 16),
               ah + (size_t)(m0 + row) * K + c * 8);
    }
#pragma unroll
    for (int u = 0; u < WCP; u++) {
        int id = tid + u * NT, row = id / CPRB, c = id % CPRB;
        cp16cg(smb + ATILE + (uint32_t)(row * LDB + c * 16),
               wh + (size_t)row * BN + c * 8);
        cp16cg(smb + ATILE + BTILE + (uint32_t)(row * LDB + c * 16),
               wh + (size_t)(K + row) * BN + c * 8);
    }
    CP_COMMIT();

    float accS[2][NTN][4], accN[2][NTN][4];
#pragma unroll
    for (int mt = 0; mt < 2; mt++)
#pragma unroll
        for (int nt = 0; nt < NTN; nt++)
#pragma unroll
            for (int q = 0; q < 4; q++) { accS[mt][nt][q] = 0.f; accN[mt][nt][q] = 0.f; }

    CP_WAIT0();
    __syncthreads();

    const uint32_t a_lrow =
        (uint32_t)(wr * 32 + (lane & 15)) * LDA + (lane >> 4) * 16;

#pragma unroll
    for (int ks = 0; ks < K / 16; ks++) {
        uint32_t ahf[2][4];
#pragma unroll
        for (int mt = 0; mt < 2; mt++)
            ldsm_x4(ahf[mt], smb + a_lrow + mt * (16 * LDA) + ks * 32);
        uint32_t wsf[NBL][4], wnf[NBL][4];
#pragma unroll
        for (int bt = 0; bt < NBL; bt++) {
            int krow = ks * 16 + (lane & 15);
            int ncol = wc * CW + bt * 16 + (lane >> 4) * 8;
            uint32_t off = (uint32_t)(krow * LDB + ncol * 2);
            ldsm_x4_t(wsf[bt], smb + ATILE + off);
            ldsm_x4_t(wnf[bt], smb + ATILE + BTILE + off);
        }
#pragma unroll
        for (int mt = 0; mt < 2; mt++)
#pragma unroll
            for (int nt = 0; nt < NTN; nt++) {
                const int g = nt >> 1, p = (nt & 1) * 2;
                mma_f16(accS[mt][nt], ahf[mt], wsf[g][p], wsf[g][p + 1]);
                mma_f16(accN[mt][nt], ahf[mt], wnf[g][p], wnf[g][p + 1]);
            }
    }

    const int g = lane >> 2, cp2 = (lane & 3) * 2;
#pragma unroll
    for (int mt = 0; mt < 2; mt++) {
        const int r0 = m0 + wr * 32 + mt * 16 + g;
#pragma unroll
        for (int nt = 0; nt < NTN; nt++) {
            const int col = wc * CW + nt * 8 + cp2;
            const float b0 = bias[col], b1 = bias[col + 1];
#pragma unroll
            for (int half = 0; half < 2; half++) {
                const size_t row = (size_t)(r0 + half * 8);
                *reinterpret_cast<float2*>(yout + row * BN + col) =
                    make_float2(accS[mt][nt][2 * half] + b0,
                                accS[mt][nt][2 * half + 1] + b1);
                *reinterpret_cast<uint32_t*>(zh + row * BN + col) =
                    packh2(accN[mt][nt][2 * half], accN[mt][nt][2 * half + 1]);
            }
        }
    }
}

// ── aggregation + optional fused next-layer projection ──
template <int BN, bool CVT, int BNP, int BK>
__global__ __launch_bounds__(512) void agg_k(
    const float* __restrict__ adjf,
    __half* __restrict__ adjh,
    const __half* __restrict__ zh,
    float* __restrict__ y,
    const __half* __restrict__ wh,
    const float* __restrict__ bias,
    float* __restrict__ out,
    __half* __restrict__ zout)
{
    constexpr int NT = 512;
    constexpr int BM = 64, NCH = MROWS / BK;
    constexpr int LDA = BK * 2 + 16;
    constexpr int ATILE = BM * LDA;
    constexpr int LDB = BN * 2 + 16;
    constexpr int BTILE = BK * LDB;
    constexpr int BOFF = 2 * ATILE;
    constexpr int CW = BN / 2, NTN = CW / 8, NBL = NTN / 2;
    constexpr int BCP = (BK * BN * 2 / 16) / NT, CPRB = BN / 8;
    constexpr int KPW = BK / 64;                   // ksteps per warp (2 or 4)
    constexpr int ACPT = BK / 64;                  // uint4 A loads per thread
    constexpr int APR = BK / 8;                    // uint4 per A row
    // fused proj constants
    constexpr int LDBP = (BNP > 0 ? BNP : 8) * 2 + 16;
    constexpr int WTILE = 128 * LDBP;
    constexpr int WOFF = BOFF + 3 * BTILE;
    constexpr int CWP = (BNP > 0 ? BNP : 8) / 4;
    constexpr int NTP = CWP / 8 > 0 ? CWP / 8 : 1;
    constexpr int NBP = NTP / 2 > 0 ? NTP / 2 : 1;

    extern __shared__ __align__(128) char sm[];
    const uint32_t smb = smem_u32(sm);
    const int tid = threadIdx.x, m0 = blockIdx.x * BM;
    const int w = tid >> 5, lane = tid & 31;
    const int kw = w >> 2, wi = w & 3;
    const int wr = wi >> 1, wc = wi & 1;

    if (BNP > 0) {
        constexpr int WCP2 = (BNP > 0 ? (128 * BNP * 2 / 16) / NT : 1);
        constexpr int CPRP = (BNP > 0 ? BNP : 8) / 8;
#pragma unroll
        for (int u = 0; u < WCP2; u++) {
            int id = tid + u * NT, row = id / CPRP, c = id % CPRP;
            cp16cg(smb + WOFF + (uint32_t)(row * LDBP + c * 16),
                   wh + (size_t)row * BNP + c * 8);
            cp16cg(smb + WOFF + WTILE + (uint32_t)(row * LDBP + c * 16),
                   wh + (size_t)(128 + row) * BNP + c * 8);
        }
    }

    float acc[2][NTN][4];
#pragma unroll
    for (int mt = 0; mt < 2; mt++)
#pragma unroll
        for (int nt = 0; nt < NTN; nt++)
#pragma unroll
            for (int q = 0; q < 4; q++) acc[mt][nt][q] = 0.f;

    float4 raf[4];
    uint4  rah[ACPT];

    auto prefA = [&](int chunk) {
        const size_t kb = (size_t)chunk * BK;
        if (CVT) {
#pragma unroll
            for (int u = 0; u < 4; u++) {
                int id = tid + u * NT, row = id >> 5, c = id & 31;
                raf[u] = *reinterpret_cast<const float4*>(
                    adjf + (size_t)(m0 + row) * MROWS + kb + c * 4);
            }
        } else {
#pragma unroll
            for (int u = 0; u < ACPT; u++) {
                int id = tid + u * NT, row = id / APR, c = id % APR;
                rah[u] = *reinterpret_cast<const uint4*>(
                    adjh + (size_t)(m0 + row) * MROWS + kb + c * 8);
            }
        }
    };
    auto commitA = [&](int sa, int chunk) {
        const size_t kb = (size_t)chunk * BK;
        if (CVT) {
#pragma unroll
            for (int u = 0; u < 4; u++) {
                int id = tid + u * NT, row = id >> 5, c = id & 31;
                uint32_t h01 = packh2(raf[u].x * A_SCALE, raf[u].y * A_SCALE);
                uint32_t h23 = packh2(raf[u].z * A_SCALE, raf[u].w * A_SCALE);
                uint32_t off = (uint32_t)(row * LDA + c * 8);
                *reinterpret_cast<uint2*>(sm + sa * ATILE + off) =
                    make_uint2(h01, h23);
                *reinterpret_cast<uint2*>(
                    adjh + (size_t)(m0 + row) * MROWS + kb + c * 4) =
                    make_uint2(h01, h23);
            }
        } else {
#pragma unroll
            for (int u = 0; u < ACPT; u++) {
                int id = tid + u * NT, row = id / APR, c = id % APR;
                *reinterpret_cast<uint4*>(sm + sa * ATILE + row * LDA + c * 16) =
                    rah[u];
            }
        }
    };
    auto issueB = [&](int chunk) {
        const uint32_t base = smb + BOFF + (chunk % 3) * BTILE;
        const size_t kb = (size_t)chunk * BK;
#pragma unroll
        for (int u = 0; u < BCP; u++) {
            int id = tid + u * NT;
            int krow = id / CPRB, c = id % CPRB;
            cp16cg(base + (uint32_t)(krow * LDB + c * 16),
                   zh + (kb + krow) * BN + c * 8);
        }
    };

    const uint32_t a_lrow =
        (uint32_t)(wr * 32 + (lane & 15)) * LDA + (lane >> 4) * 16;

    auto compute = [&](int sa, int sb) {
        const uint32_t ab = smb + sa * ATILE;
        const uint32_t bb = smb + BOFF + sb * BTILE;
#pragma unroll
        for (int s = 0; s < KPW; s++) {
            const int ks = kw * KPW + s;
            uint32_t ahf[2][4];
#pragma unroll
            for (int mt = 0; mt < 2; mt++)
                ldsm_x4(ahf[mt], ab + a_lrow + mt * (16 * LDA) + ks * 32);
            uint32_t zb[NBL][4];
#pragma unroll
            for (int bt = 0; bt < NBL; bt++) {
                int krow = ks * 16 + (lane & 15);
                int ncol = wc * CW + bt * 16 + (lane >> 4) * 8;
                ldsm_x4_t(zb[bt], bb + (uint32_t)(krow * LDB + ncol * 2));
            }
#pragma unroll
            for (int mt = 0; mt < 2; mt++)
#pragma unroll
                for (int nt = 0; nt < NTN; nt++) {
                    const int g = nt >> 1, p = (nt & 1) * 2;
                    mma_f16(acc[mt][nt], ahf[mt], zb[g][p], zb[g][p + 1]);
                }
        }
    };

    issueB(0); CP_COMMIT();
    issueB(1); CP_COMMIT();
    prefA(0);
    commitA(0, 0);
    prefA(1);

    for (int i = 0; i < NCH; i++) {
        const int sa = i & 1, sb = i % 3;
        CP_WAIT1();
        __syncthreads();
        if (i + 2 < NCH) { issueB(i + 2); CP_COMMIT(); }
        compute(sa, sb);
        if (i + 1 < NCH) {
            commitA((i + 1) & 1, i + 1);
            if (i + 2 < NCH) prefA(i + 2);
        }
    }

    // merge: single publish (kw 1..3 disjoint), kw==0 sums + epilogue
    __syncthreads();
    float* ps = reinterpret_cast<float*>(sm);
    constexpr int PBASE = ATILE / 4;
    constexpr int PSZ = 1024 * NTN;
    if (kw > 0) {
#pragma unroll
        for (int mt = 0; mt < 2; mt++)
#pragma unroll
            for (int nt = 0; nt < NTN; nt++)
#pragma unroll
                for (int q = 0; q < 4; q++)
                    ps[PBASE + (kw - 1) * PSZ +
                       ((((wi * 2 + mt) * NTN + nt) * 4) + q) * 32 + lane] =
                        acc[mt][nt][q];
    }
    __syncthreads();
    if (kw == 0) {
        const int g = lane >> 2, cp2 = (lane & 3) * 2;
#pragma unroll
        for (int mt = 0; mt < 2; mt++) {
            const int r0 = m0 + wr * 32 + mt * 16 + g;
#pragma unroll
            for (int nt = 0; nt < NTN; nt++) {
                const int col = wc * CW + nt * 8 + cp2;
                float p[4];
#pragma unroll
                for (int q = 0; q < 4; q++) {
                    int idx = ((((wi * 2 + mt) * NTN + nt) * 4) + q) * 32 + lane;
                    p[q] = acc[mt][nt][q] + ps[PBASE + idx] +
                           ps[PBASE + PSZ + idx] + ps[PBASE + 2 * PSZ + idx];
                }
#pragma unroll
                for (int half = 0; half < 2; half++) {
                    const size_t row = (size_t)(r0 + half * 8);
                    float2 yv = *reinterpret_cast<const float2*>(y + row * BN + col);
                    float v0 = p[2 * half + 0] * A_INV + yv.x;
                    float v1 = p[2 * half + 1] * A_INV + yv.y;
                    if (BNP > 0) {
                        v0 = fmaxf(v0, 0.f); v1 = fmaxf(v1, 0.f);
                        *reinterpret_cast<uint32_t*>(
                            sm + (uint32_t)((r0 + half * 8 - m0) * LDA + col * 2)) =
                            packh2(v0, v1);
                    } else {
                        *reinterpret_cast<float2*>(out + row * BN + col) =
                            make_float2(v0, v1);
                    }
                }
            }
        }
    }

    // fused projection (8 warps)
    if (BNP > 0) {
        __syncthreads();
        if (w < 8) {
            const int pwr = w >> 2, pwc = w & 3;
            float accS[2][NTP][4], accN[2][NTP][4];
#pragma unroll
            for (int mt = 0; mt < 2; mt++)
#pragma unroll
                for (int nt = 0; nt < NTP; nt++)
#pragma unroll
                    for (int q = 0; q < 4; q++) { accS[mt][nt][q] = 0.f; accN[mt][nt][q] = 0.f; }

            const uint32_t pa_lrow =
                (uint32_t)(pwr * 32 + (lane & 15)) * LDA + (lane >> 4) * 16;
#pragma unroll
            for (int ks = 0; ks < 8; ks++) {
                uint32_t ahf[2][4];
#pragma unroll
                for (int mt = 0; mt < 2; mt++)
                    ldsm_x4(ahf[mt], smb + pa_lrow + mt * (16 * LDA) + ks * 32);
                uint32_t wsf[NBP][4], wnf[NBP][4];
#pragma unroll
                for (int bt = 0; bt < NBP; bt++) {
                    int krow = ks * 16 + (lane & 15);
                    int ncol = pwc * CWP + bt * 16 + (lane >> 4) * 8;
                    uint32_t off = (uint32_t)(krow * LDBP + ncol * 2);
                    ldsm_x4_t(wsf[bt], smb + WOFF + off);
                    ldsm_x4_t(wnf[bt], smb + WOFF + WTILE + off);
                }
#pragma unroll
                for (int mt = 0; mt < 2; mt++)
#pragma unroll
                    for (int nt = 0; nt < NTP; nt++) {
                        const int g = nt >> 1, p = (nt & 1) * 2;
                        mma_f16(accS[mt][nt], ahf[mt], wsf[g][p], wsf[g][p + 1]);
                        mma_f16(accN[mt][nt], ahf[mt], wnf[g][p], wnf[g][p + 1]);
                    }
            }
            const int g = lane >> 2, cp2 = (lane & 3) * 2;
#pragma unroll
            for (int mt = 0; mt < 2; mt++) {
                const int r0 = m0 + pwr * 32 + mt * 16 + g;
#pragma unroll
                for (int nt = 0; nt < NTP; nt++) {
                    const int col = pwc * CWP + nt * 8 + cp2;
                    const float b0 = bias[col], b1 = bias[col + 1];
#pragma unroll
                    for (int half = 0; half < 2; half++) {
                        const size_t row = (size_t)(r0 + half * 8);
                        *reinterpret_cast<float2*>(y + row * BNP + col) =
                            make_float2(accS[mt][nt][2 * half] + b0,
                                        accS[mt][nt][2 * half + 1] + b1);
                        *reinterpret_cast<uint32_t*>(zout + row * BNP + col) =
                            packh2(accN[mt][nt][2 * half],
                                   accN[mt][nt][2 * half + 1]);
                    }
                }
            }
        }
    }
}

extern "C" void kernel_launch(void* const* d_in, const int* in_sizes, int n_in,
                              void* d_out, int out_size)
{
    const float* x   = (const float*)d_in[0];
    const float* adj = (const float*)d_in[1];
    const float* W1  = (const float*)d_in[2];
    const float* b1  = (const float*)d_in[3];
    const float* W2  = (const float*)d_in[4];
    const float* b2  = (const float*)d_in[5];
    const float* W3  = (const float*)d_in[6];
    const float* b3  = (const float*)d_in[7];
    const float* W4  = (const float*)d_in[8];
    const float* b4  = (const float*)d_in[9];
    float* out = (float*)d_out;

    float* y;
    __half *zha, *zhb, *xh, *adjh, *w1h, *w2h, *w3h, *w4h;
    cudaGetSymbolAddress((void**)&y,    g_y);
    cudaGetSymbolAddress((void**)&zha,  g_zha);
    cudaGetSymbolAddress((void**)&zhb,  g_zhb);
    cudaGetSymbolAddress((void**)&xh,   g_xh);
    cudaGetSymbolAddress((void**)&adjh, g_adjh);
    cudaGetSymbolAddress((void**)&w1h,  g_w1h);
    cudaGetSymbolAddress((void**)&w2h,  g_w2h);
    cudaGetSymbolAddress((void**)&w3h,  g_w3h);
    cudaGetSymbolAddress((void**)&w4h,  g_w4h);

    constexpr int BASE128 = 2 * (64 * 272) + 3 * (128 * (128 * 2 + 16)); // 139264
    constexpr int SMA_P128 = BASE128 + 2 * (128 * (128 * 2 + 16));       // 208896
    constexpr int SMA_P64  = BASE128 + 2 * (128 * (64 * 2 + 16));        // 176128
    constexpr int BASE64_256 = 2 * (64 * 528) + 3 * (256 * (64 * 2 + 16)); // 178176
    constexpr int SP1 = 64 * (256 * 2 + 16) + 2 * (256 * (128 * 2 + 16)); // 173056
    cudaFuncSetAttribute(agg_k<128, true, 128, 128>,  cudaFuncAttributeMaxDynamicSharedMemorySize, SMA_P128);
    cudaFuncSetAttribute(agg_k<128, false, 128, 128>, cudaFuncAttributeMaxDynamicSharedMemorySize, SMA_P128);
    cudaFuncSetAttribute(agg_k<128, false, 64, 128>,  cudaFuncAttributeMaxDynamicSharedMemorySize, SMA_P64);
    cudaFuncSetAttribute(agg_k<64,  false, 0, 256>,   cudaFuncAttributeMaxDynamicSharedMemorySize, BASE64_256);
    cudaFuncSetAttribute(projmma_k<256, 128>, cudaFuncAttributeMaxDynamicSharedMemorySize, SP1);

    const dim3 ag(MROWS / 64);

    cvt_k<<<8192, 256>>>(x, W1, W2, W3, W4, xh, w1h, w2h, w3h, w4h);

    projmma_k<256, 128><<<ag, 256, SP1>>>(xh, w1h, b1, y, zha);
    agg_k<128, true, 128, 128><<<ag, 512, SMA_P128>>>(adj, adjh, zha, y, w2h, b2, nullptr, zhb);
    agg_k<128, false, 128, 128><<<ag, 512, SMA_P128>>>(nullptr, adjh, zhb, y, w3h, b3, nullptr, zha);
    agg_k<128, false, 64, 128><<<ag, 512, SMA_P64>>>(nullptr, adjh, zha, y, w4h, b4, nullptr, zhb);
    agg_k<64, false, 0, 256><<<ag, 512, BASE64_256>>>(nullptr, adjh, zhb, y, nullptr, nullptr, out, nullptr);
}